// round 1
// baseline (speedup 1.0000x reference)
#include <cuda_runtime.h>
#include <cuda_bf16.h>
#include <cstdint>
#include <cstddef>

// ---------------------------------------------------------------------------
// Problem constants: B=2, T=2048, D=1024, NH=16, HD=64, HID=4096, CD=1024
// ---------------------------------------------------------------------------
#define BT 4096            // B*T rows
#define DD 1024
#define NHEAD 16
#define HDIM 64
#define HID 4096

// ---------------------------------------------------------------------------
// Device scratch (static global allocations; no cudaMalloc allowed)
// ---------------------------------------------------------------------------
__device__ float g_ada [2 * 6144];
__device__ float g_h   [(size_t)BT * DD];
__device__ float g_qkv [(size_t)BT * 3 * DD];
__device__ float g_q   [(size_t)BT * DD];
__device__ float g_k   [(size_t)BT * DD];
__device__ float g_v   [(size_t)BT * DD];
__device__ float g_attn[(size_t)BT * DD];
__device__ float g_xa  [(size_t)BT * DD];
__device__ float g_h2  [(size_t)BT * DD];
__device__ float g_fc1 [(size_t)BT * 2 * HID];
__device__ float g_mid [(size_t)BT * HID];

// ---------------------------------------------------------------------------
// adaLN: ada[b][n] = sum_k silu(cond[b][k]) * ada_w[n][k] + ada_b[n]
// One warp per output element (12288 warps).
// ---------------------------------------------------------------------------
__global__ void __launch_bounds__(256) ada_kernel(
    const float* __restrict__ cond, const float* __restrict__ W,
    const float* __restrict__ bias, float* __restrict__ ada)
{
    __shared__ float sc[2048];
    int tid = threadIdx.x;
    for (int i = tid; i < 2048; i += 256) {
        float c = cond[i];
        sc[i] = c / (1.0f + expf(-c));
    }
    __syncthreads();
    int warp = blockIdx.x * 8 + (tid >> 5);
    int lane = tid & 31;
    int b = warp / 6144;
    int col = warp % 6144;
    const float* wr = W + (size_t)col * 1024;
    const float* cr = sc + b * 1024;
    float acc = 0.0f;
    #pragma unroll
    for (int i = 0; i < 8; i++) {
        int k = lane * 4 + i * 128;
        float4 wv = *(const float4*)(wr + k);
        acc += cr[k] * wv.x + cr[k + 1] * wv.y + cr[k + 2] * wv.z + cr[k + 3] * wv.w;
    }
    #pragma unroll
    for (int o = 16; o; o >>= 1) acc += __shfl_xor_sync(0xffffffffu, acc, o);
    if (lane == 0) ada[warp] = acc + bias[col];
}

// ---------------------------------------------------------------------------
// RMSNorm + modulate: out = x*rsqrt(mean(x^2)+eps)*w*(1+sc) + sh
// One block (256 thr) per row; each thread handles 4 consecutive elements.
// ---------------------------------------------------------------------------
__global__ void __launch_bounds__(256) norm_mod_kernel(
    const float* __restrict__ x, float* __restrict__ out,
    const float* __restrict__ w, const float* __restrict__ ada,
    int sh_off, int sc_off)
{
    int row = blockIdx.x;
    int b = row >> 11;                 // rows-per-batch = 2048
    int tid = threadIdx.x;
    const float* xr = x + (size_t)row * 1024;
    float4 v = *(const float4*)(xr + tid * 4);
    float ss = v.x * v.x + v.y * v.y + v.z * v.z + v.w * v.w;
    #pragma unroll
    for (int o = 16; o; o >>= 1) ss += __shfl_xor_sync(0xffffffffu, ss, o);
    __shared__ float red[8];
    if ((tid & 31) == 0) red[tid >> 5] = ss;
    __syncthreads();
    float tot = 0.0f;
    #pragma unroll
    for (int i = 0; i < 8; i++) tot += red[i];
    float inv = rsqrtf(tot * (1.0f / 1024.0f) + 1e-6f);
    const float* sh = ada + b * 6144 + sh_off;
    const float* sc = ada + b * 6144 + sc_off;
    int d = tid * 4;
    float4 o4;
    o4.x = v.x * inv * w[d]     * (1.0f + sc[d])     + sh[d];
    o4.y = v.y * inv * w[d + 1] * (1.0f + sc[d + 1]) + sh[d + 1];
    o4.z = v.z * inv * w[d + 2] * (1.0f + sc[d + 2]) + sh[d + 2];
    o4.w = v.w * inv * w[d + 3] * (1.0f + sc[d + 3]) + sh[d + 3];
    *(float4*)(out + (size_t)row * 1024 + d) = o4;
}

// ---------------------------------------------------------------------------
// Generic FP32 GEMM:  C[M,N] = A[M,K] @ Bw[N,K]^T  (+bias) (+res + gvec*( ))
// 128x128 block tile, BK=16, 8x8 per thread, smem stored K-major (transposed).
// ---------------------------------------------------------------------------
#define GBM 128
#define GBN 128
#define GBK 16
__global__ void __launch_bounds__(256) gemm_nt(
    const float* __restrict__ A, const float* __restrict__ Bw,
    float* __restrict__ C, int M, int N, int K,
    const float* __restrict__ bias, const float* __restrict__ res,
    const float* __restrict__ gvec, int goff)
{
    __shared__ float As[GBK][GBM + 4];
    __shared__ float Bs[GBK][GBN + 4];
    int tid = threadIdx.x;
    int tc = tid & 15, tr = tid >> 4;
    int n0 = blockIdx.x * GBN, m0 = blockIdx.y * GBM;
    float acc[8][8];
    #pragma unroll
    for (int i = 0; i < 8; i++)
        #pragma unroll
        for (int j = 0; j < 8; j++) acc[i][j] = 0.0f;

    const float* Ab = A + (size_t)m0 * K;
    const float* Bb = Bw + (size_t)n0 * K;

    for (int kb = 0; kb < K; kb += GBK) {
        #pragma unroll
        for (int i = 0; i < 2; i++) {
            int f = tid + i * 256;           // float4 tile index 0..511
            int row = f >> 2;
            int k4 = (f & 3) * 4;
            float4 av = *(const float4*)(Ab + (size_t)row * K + kb + k4);
            As[k4 + 0][row] = av.x; As[k4 + 1][row] = av.y;
            As[k4 + 2][row] = av.z; As[k4 + 3][row] = av.w;
            float4 bv = *(const float4*)(Bb + (size_t)row * K + kb + k4);
            Bs[k4 + 0][row] = bv.x; Bs[k4 + 1][row] = bv.y;
            Bs[k4 + 2][row] = bv.z; Bs[k4 + 3][row] = bv.w;
        }
        __syncthreads();
        #pragma unroll
        for (int kk = 0; kk < GBK; kk++) {
            float a[8], bb[8];
            *(float4*)&a[0]  = *(const float4*)&As[kk][8 * tr];
            *(float4*)&a[4]  = *(const float4*)&As[kk][8 * tr + 4];
            *(float4*)&bb[0] = *(const float4*)&Bs[kk][8 * tc];
            *(float4*)&bb[4] = *(const float4*)&Bs[kk][8 * tc + 4];
            #pragma unroll
            for (int i = 0; i < 8; i++)
                #pragma unroll
                for (int j = 0; j < 8; j++)
                    acc[i][j] += a[i] * bb[j];
        }
        __syncthreads();
    }

    #pragma unroll
    for (int i = 0; i < 8; i++) {
        int gm = m0 + 8 * tr + i;
        int bb = gm >> 11;
        #pragma unroll
        for (int j = 0; j < 8; j++) {
            int gn = n0 + 8 * tc + j;
            float v = acc[i][j];
            if (bias) v += bias[gn];
            if (gvec) v = res[(size_t)gm * N + gn] + gvec[bb * 6144 + goff + gn] * v;
            C[(size_t)gm * N + gn] = v;
        }
    }
}

// ---------------------------------------------------------------------------
// QKV post-processing: per (b,t,nh) head of 64: RMSNorm(q/k) + 2D RoPE,
// transpose to (B,NH,T,HD). One warp per head (lane handles pair 2l,2l+1).
// ---------------------------------------------------------------------------
__global__ void __launch_bounds__(256) qkv_post_kernel(
    const float* __restrict__ qkv, float* __restrict__ q, float* __restrict__ k,
    float* __restrict__ v, const float* __restrict__ qw,
    const float* __restrict__ kw, const int* __restrict__ widthp)
{
    int width = *widthp;
    int gw = blockIdx.x * 8 + (threadIdx.x >> 5);
    int lane = threadIdx.x & 31;
    int nh = gw & 15;
    int t  = (gw >> 4) & 2047;
    int b  = gw >> 15;
    const float* src = qkv + (size_t)(b * 2048 + t) * 3072;
    int hd0 = 2 * lane;

    float2 qv = *(const float2*)(src + nh * 64 + hd0);
    float2 kv = *(const float2*)(src + 1024 + nh * 64 + hd0);
    float2 vv = *(const float2*)(src + 2048 + nh * 64 + hd0);

    // RMSNorm q over 64 elems
    float ssq = qv.x * qv.x + qv.y * qv.y;
    float ssk = kv.x * kv.x + kv.y * kv.y;
    #pragma unroll
    for (int o = 16; o; o >>= 1) {
        ssq += __shfl_xor_sync(0xffffffffu, ssq, o);
        ssk += __shfl_xor_sync(0xffffffffu, ssk, o);
    }
    float qi = rsqrtf(ssq * (1.0f / 64.0f) + 1e-6f);
    float ki = rsqrtf(ssk * (1.0f / 64.0f) + 1e-6f);
    float qx = qv.x * qi * qw[hd0], qy = qv.y * qi * qw[hd0 + 1];
    float kx = kv.x * ki * kw[hd0], ky = kv.y * ki * kw[hd0 + 1];

    // RoPE: lanes 0..15 -> y axis, lanes 16..31 -> x axis; freq idx = lane%16
    int yy = t / width, xx = t % width;
    int j = lane & 15;
    float coord = (float)((lane < 16) ? yy : xx);
    float freq = powf(10000.0f, -(float)j * (1.0f / 16.0f));
    float ang = coord * freq;
    float s, c;
    sincosf(ang, &s, &c);
    float qox = qx * c - qy * s;
    float qoy = qy * c + qx * s;
    float kox = kx * c - ky * s;
    float koy = ky * c + kx * s;

    size_t base = ((size_t)((b * 16 + nh) * 2048 + t)) * 64 + hd0;
    *(float2*)(q + base) = make_float2(qox, qoy);
    *(float2*)(k + base) = make_float2(kox, koy);
    *(float2*)(v + base) = make_float2(vv.x, vv.y);
}

// ---------------------------------------------------------------------------
// FP32 flash attention. 64 queries x 64 keys per tile, HD=64.
// 256 threads as 16x16; each thread owns a 4x4 micro-tile.
// smem tiles stored d-major (qs,ks) / j-major (vs,ps), row stride 68.
// ---------------------------------------------------------------------------
#define ATT_STRIDE 68
__global__ void __launch_bounds__(256) attn_kernel(
    const float* __restrict__ Q, const float* __restrict__ K,
    const float* __restrict__ V, float* __restrict__ O)
{
    extern __shared__ float sm[];
    float* qs = sm;                       // [d][r]
    float* ks = sm + 64 * ATT_STRIDE;     // [d][c]
    float* vs = sm + 2 * 64 * ATT_STRIDE; // [j][c]
    float* ps = sm + 3 * 64 * ATT_STRIDE; // [j][r]

    int tid = threadIdx.x;
    int tx = tid & 15, ty = tid >> 4;
    int qt = blockIdx.x, h = blockIdx.y, b = blockIdx.z;
    const size_t bh = ((size_t)(b * 16 + h)) * 2048 * 64;

    // load Q tile, pre-scaled by 1/sqrt(HD), store transposed [d][r]
    #pragma unroll
    for (int i = 0; i < 4; i++) {
        int f = tid + i * 256;
        int r = f >> 4, d0 = (f & 15) * 4;
        float4 qv = *(const float4*)(Q + bh + (size_t)(qt * 64 + r) * 64 + d0);
        qs[(d0 + 0) * ATT_STRIDE + r] = qv.x * 0.125f;
        qs[(d0 + 1) * ATT_STRIDE + r] = qv.y * 0.125f;
        qs[(d0 + 2) * ATT_STRIDE + r] = qv.z * 0.125f;
        qs[(d0 + 3) * ATT_STRIDE + r] = qv.w * 0.125f;
    }

    float m[4], l[4], acc[4][4];
    #pragma unroll
    for (int i = 0; i < 4; i++) {
        m[i] = -1e30f; l[i] = 0.0f;
        #pragma unroll
        for (int jj = 0; jj < 4; jj++) acc[i][jj] = 0.0f;
    }

    for (int kt = 0; kt < 32; kt++) {
        #pragma unroll
        for (int i = 0; i < 4; i++) {
            int f = tid + i * 256;
            int r = f >> 4, d0 = (f & 15) * 4;
            float4 kv = *(const float4*)(K + bh + (size_t)(kt * 64 + r) * 64 + d0);
            ks[(d0 + 0) * ATT_STRIDE + r] = kv.x;
            ks[(d0 + 1) * ATT_STRIDE + r] = kv.y;
            ks[(d0 + 2) * ATT_STRIDE + r] = kv.z;
            ks[(d0 + 3) * ATT_STRIDE + r] = kv.w;
            float4 vv = *(const float4*)(V + bh + (size_t)(kt * 64 + r) * 64 + d0);
            *(float4*)&vs[r * ATT_STRIDE + d0] = vv;
        }
        __syncthreads();

        // S = q . k^T
        float s[4][4];
        #pragma unroll
        for (int i = 0; i < 4; i++)
            #pragma unroll
            for (int jj = 0; jj < 4; jj++) s[i][jj] = 0.0f;
        #pragma unroll 8
        for (int d = 0; d < 64; d++) {
            float4 a  = *(const float4*)&qs[d * ATT_STRIDE + 4 * ty];
            float4 bk = *(const float4*)&ks[d * ATT_STRIDE + 4 * tx];
            float av[4] = {a.x, a.y, a.z, a.w};
            float bv[4] = {bk.x, bk.y, bk.z, bk.w};
            #pragma unroll
            for (int i = 0; i < 4; i++)
                #pragma unroll
                for (int jj = 0; jj < 4; jj++)
                    s[i][jj] += av[i] * bv[jj];
        }

        // online softmax (rows shared across the 16 threads with equal ty)
        #pragma unroll
        for (int i = 0; i < 4; i++) {
            float rm = fmaxf(fmaxf(s[i][0], s[i][1]), fmaxf(s[i][2], s[i][3]));
            #pragma unroll
            for (int o = 8; o; o >>= 1) rm = fmaxf(rm, __shfl_xor_sync(0xffffffffu, rm, o));
            float mn = fmaxf(m[i], rm);
            float corr = __expf(m[i] - mn);
            float rsum = 0.0f;
            #pragma unroll
            for (int jj = 0; jj < 4; jj++) {
                s[i][jj] = __expf(s[i][jj] - mn);
                rsum += s[i][jj];
            }
            #pragma unroll
            for (int o = 8; o; o >>= 1) rsum += __shfl_xor_sync(0xffffffffu, rsum, o);
            l[i] = l[i] * corr + rsum;
            m[i] = mn;
            #pragma unroll
            for (int jj = 0; jj < 4; jj++) {
                acc[i][jj] *= corr;
                ps[(4 * tx + jj) * ATT_STRIDE + 4 * ty + i] = s[i][jj];
            }
        }
        __syncthreads();

        // O += P @ V
        #pragma unroll 8
        for (int jk = 0; jk < 64; jk++) {
            float4 pv = *(const float4*)&ps[jk * ATT_STRIDE + 4 * ty];
            float4 vv = *(const float4*)&vs[jk * ATT_STRIDE + 4 * tx];
            float pa[4] = {pv.x, pv.y, pv.z, pv.w};
            float va[4] = {vv.x, vv.y, vv.z, vv.w};
            #pragma unroll
            for (int i = 0; i < 4; i++)
                #pragma unroll
                for (int jj = 0; jj < 4; jj++)
                    acc[i][jj] += pa[i] * va[jj];
        }
        __syncthreads();
    }

    #pragma unroll
    for (int i = 0; i < 4; i++) {
        float invl = 1.0f / l[i];
        int t = qt * 64 + 4 * ty + i;
        #pragma unroll
        for (int jj = 0; jj < 4; jj++) {
            O[(size_t)(b * 2048 + t) * 1024 + h * 64 + 4 * tx + jj] = acc[i][jj] * invl;
        }
    }
}

// ---------------------------------------------------------------------------
// MLP activation: mid = value * silu(gate)
// ---------------------------------------------------------------------------
__global__ void __launch_bounds__(256) mlp_act_kernel(
    const float* __restrict__ fc1, float* __restrict__ mid)
{
    int f = blockIdx.x * 256 + threadIdx.x;     // float4 index over (row, j/4)
    int row = f >> 10;
    int jcol = (f & 1023) * 4;
    float4 v = *(const float4*)(fc1 + (size_t)row * 8192 + jcol);
    float4 g = *(const float4*)(fc1 + (size_t)row * 8192 + 4096 + jcol);
    float4 o;
    o.x = v.x * g.x / (1.0f + __expf(-g.x));
    o.y = v.y * g.y / (1.0f + __expf(-g.y));
    o.z = v.z * g.z / (1.0f + __expf(-g.z));
    o.w = v.w * g.w / (1.0f + __expf(-g.w));
    *(float4*)(mid + (size_t)row * 4096 + jcol) = o;
}

// ---------------------------------------------------------------------------
// Launch
// ---------------------------------------------------------------------------
extern "C" void kernel_launch(void* const* d_in, const int* in_sizes, int n_in,
                              void* d_out, int out_size)
{
    const float* x        = (const float*)d_in[0];
    const float* cond     = (const float*)d_in[1];
    const float* norm1_w  = (const float*)d_in[2];
    const float* qkv_w    = (const float*)d_in[3];
    const float* q_norm_w = (const float*)d_in[4];
    const float* k_norm_w = (const float*)d_in[5];
    const float* proj_w   = (const float*)d_in[6];
    const float* proj_b   = (const float*)d_in[7];
    const float* norm2_w  = (const float*)d_in[8];
    const float* fc1_w    = (const float*)d_in[9];
    const float* fc1_b    = (const float*)d_in[10];
    const float* fc2_w    = (const float*)d_in[11];
    const float* fc2_b    = (const float*)d_in[12];
    const float* ada_w    = (const float*)d_in[13];
    const float* ada_b    = (const float*)d_in[14];
    const int*   widthp   = (const int*)d_in[16];
    float* out = (float*)d_out;

    float *p_ada, *p_h, *p_qkv, *p_q, *p_k, *p_v, *p_attn, *p_xa, *p_h2, *p_fc1, *p_mid;
    cudaGetSymbolAddress((void**)&p_ada, g_ada);
    cudaGetSymbolAddress((void**)&p_h, g_h);
    cudaGetSymbolAddress((void**)&p_qkv, g_qkv);
    cudaGetSymbolAddress((void**)&p_q, g_q);
    cudaGetSymbolAddress((void**)&p_k, g_k);
    cudaGetSymbolAddress((void**)&p_v, g_v);
    cudaGetSymbolAddress((void**)&p_attn, g_attn);
    cudaGetSymbolAddress((void**)&p_xa, g_xa);
    cudaGetSymbolAddress((void**)&p_h2, g_h2);
    cudaGetSymbolAddress((void**)&p_fc1, g_fc1);
    cudaGetSymbolAddress((void**)&p_mid, g_mid);

    int attn_smem = 4 * 64 * ATT_STRIDE * (int)sizeof(float);
    cudaFuncSetAttribute(attn_kernel, cudaFuncAttributeMaxDynamicSharedMemorySize, attn_smem);

    // 1) adaLN vector
    ada_kernel<<<1536, 256>>>(cond, ada_w, ada_b, p_ada);
    // 2) norm1 + modulate (sh_a @ 0, sc_a @ 1024)
    norm_mod_kernel<<<4096, 256>>>(x, p_h, norm1_w, p_ada, 0, 1024);
    // 3) QKV GEMM
    gemm_nt<<<dim3(3072 / GBN, 4096 / GBM), 256>>>(p_h, qkv_w, p_qkv,
        4096, 3072, 1024, nullptr, nullptr, nullptr, 0);
    // 4) QK norm + RoPE + transpose
    qkv_post_kernel<<<8192, 256>>>(p_qkv, p_q, p_k, p_v, q_norm_w, k_norm_w, widthp);
    // 5) attention
    attn_kernel<<<dim3(32, 16, 2), 256, attn_smem>>>(p_q, p_k, p_v, p_attn);
    // 6) proj GEMM + residual + gate (g_a @ 2048)
    gemm_nt<<<dim3(1024 / GBN, 4096 / GBM), 256>>>(p_attn, proj_w, p_xa,
        4096, 1024, 1024, proj_b, x, p_ada, 2 * 1024);
    // 7) norm2 + modulate (sh_m @ 3072, sc_m @ 4096)
    norm_mod_kernel<<<4096, 256>>>(p_xa, p_h2, norm2_w, p_ada, 3 * 1024, 4 * 1024);
    // 8) fc1 GEMM (+bias)
    gemm_nt<<<dim3(8192 / GBN, 4096 / GBM), 256>>>(p_h2, fc1_w, p_fc1,
        4096, 8192, 1024, fc1_b, nullptr, nullptr, 0);
    // 9) value * silu(gate)
    mlp_act_kernel<<<16384, 256>>>(p_fc1, p_mid);
    // 10) fc2 GEMM + residual + gate (g_m @ 5120) -> out
    gemm_nt<<<dim3(1024 / GBN, 4096 / GBM), 256>>>(p_mid, fc2_w, out,
        4096, 1024, 4096, fc2_b, p_xa, p_ada, 5 * 1024);
}

// round 3
// speedup vs baseline: 1.9234x; 1.9234x over previous
#include <cuda_runtime.h>
#include <cuda_bf16.h>
#include <cstdint>
#include <cstddef>

// ---------------------------------------------------------------------------
// Problem constants: B=2, T=2048, D=1024, NH=16, HD=64, HID=4096, CD=1024
// ---------------------------------------------------------------------------
#define BT 4096
#define DD 1024
#define HID 4096

// ---------------------------------------------------------------------------
// Device scratch
// ---------------------------------------------------------------------------
__device__ float g_ada [2 * 6144];
__device__ float g_h   [(size_t)BT * DD];
__device__ float g_qkv [(size_t)BT * 3 * DD];
__device__ float g_q   [(size_t)BT * DD];
__device__ float g_k   [(size_t)BT * DD];
__device__ float g_v   [(size_t)BT * DD];
__device__ float g_attn[(size_t)BT * DD];
__device__ float g_xa  [(size_t)BT * DD];
__device__ float g_h2  [(size_t)BT * DD];
__device__ float g_fc1 [(size_t)BT * 2 * HID];
__device__ float g_mid [(size_t)BT * HID];

// ---------------------------------------------------------------------------
// tf32 helpers (base PTX only — no 'a'-suffix features)
// ---------------------------------------------------------------------------
__device__ __forceinline__ uint32_t f2tf32(float x) {
    uint32_t u;
    asm("cvt.rna.tf32.f32 %0, %1;" : "=r"(u) : "f"(x));
    return u;
}
__device__ __forceinline__ void mma_tf32(float* c, const uint32_t* a, const uint32_t* b) {
    asm volatile(
        "mma.sync.aligned.m16n8k8.row.col.f32.tf32.tf32.f32 "
        "{%0,%1,%2,%3}, {%4,%5,%6,%7}, {%8,%9}, {%0,%1,%2,%3};"
        : "+f"(c[0]), "+f"(c[1]), "+f"(c[2]), "+f"(c[3])
        : "r"(a[0]), "r"(a[1]), "r"(a[2]), "r"(a[3]), "r"(b[0]), "r"(b[1]));
}

// ---------------------------------------------------------------------------
// TF32 tensor-core GEMM: C[M,N] = A[M,K] @ Bw[N,K]^T (+bias)(+res+gvec*())
// CTA tile 128x128, BK=32. 8 warps (2M x 4N), warp tile 64x32.
// SMEM row-major, row stride 36 words (conflict-free frag loads + STS.128).
// ---------------------------------------------------------------------------
#define GSTRIDE 36
#define GSTAGEW (128 * GSTRIDE)            // words per operand stage (4608)
#define GT_DSMEM (4 * GSTAGEW * 4)         // A0,B0,A1,B1 = 73728 bytes
__global__ void __launch_bounds__(256) gemm_mma(
    const float* __restrict__ A, const float* __restrict__ Bw,
    float* __restrict__ C, int M, int N, int K,
    const float* __restrict__ bias, const float* __restrict__ res,
    const float* __restrict__ gvec, int goff)
{
    extern __shared__ uint32_t sm4[];
    int tid = threadIdx.x;
    int wid = tid >> 5, lane = tid & 31;
    int gr = lane >> 2, tg = lane & 3;
    int wm = wid >> 2, wn = wid & 3;       // warp grid 2 x 4
    int m0 = blockIdx.y * 128, n0 = blockIdx.x * 128;

    const float* Ab = A + (size_t)m0 * K;
    const float* Bb = Bw + (size_t)n0 * K;
    const int nk = K >> 5;

    float acc[4][4][4];
    #pragma unroll
    for (int i = 0; i < 4; i++)
        #pragma unroll
        for (int j = 0; j < 4; j++)
            #pragma unroll
            for (int r = 0; r < 4; r++) acc[i][j][r] = 0.0f;

    float4 pa[4], pb[4];

    // ---- prefetch tile 0 ----
    #pragma unroll
    for (int j = 0; j < 4; j++) {
        int id = tid + j * 256; int r = id >> 3; int c4 = (id & 7) * 4;
        pa[j] = *(const float4*)(Ab + (size_t)r * K + c4);
        pb[j] = *(const float4*)(Bb + (size_t)r * K + c4);
    }
    // ---- store tile 0 -> stage 0 ----
    {
        uint32_t* As = sm4;
        uint32_t* Bs = sm4 + GSTAGEW;
        #pragma unroll
        for (int j = 0; j < 4; j++) {
            int id = tid + j * 256; int r = id >> 3; int c4 = (id & 7) * 4;
            *(uint4*)(As + r * GSTRIDE + c4) =
                make_uint4(f2tf32(pa[j].x), f2tf32(pa[j].y), f2tf32(pa[j].z), f2tf32(pa[j].w));
            *(uint4*)(Bs + r * GSTRIDE + c4) =
                make_uint4(f2tf32(pb[j].x), f2tf32(pb[j].y), f2tf32(pb[j].z), f2tf32(pb[j].w));
        }
    }
    // ---- prefetch tile 1 ----
    if (nk > 1) {
        #pragma unroll
        for (int j = 0; j < 4; j++) {
            int id = tid + j * 256; int r = id >> 3; int c4 = (id & 7) * 4;
            pa[j] = *(const float4*)(Ab + (size_t)r * K + 32 + c4);
            pb[j] = *(const float4*)(Bb + (size_t)r * K + 32 + c4);
        }
    }
    __syncthreads();

    int am = wm * 64;
    int bn = wn * 32;

    for (int it = 0; it < nk; it++) {
        int s = it & 1;
        const uint32_t* As = sm4 + s * 2 * GSTAGEW;
        const uint32_t* Bs = As + GSTAGEW;

        #pragma unroll
        for (int ks = 0; ks < 4; ks++) {
            int kc = ks * 8 + tg;
            uint32_t af[4][4], bf[4][2];
            #pragma unroll
            for (int i = 0; i < 4; i++) {
                int mr = (am + i * 16 + gr) * GSTRIDE;
                af[i][0] = As[mr + kc];
                af[i][1] = As[mr + 8 * GSTRIDE + kc];
                af[i][2] = As[mr + kc + 4];
                af[i][3] = As[mr + 8 * GSTRIDE + kc + 4];
            }
            #pragma unroll
            for (int j = 0; j < 4; j++) {
                int nr = (bn + j * 8 + gr) * GSTRIDE;
                bf[j][0] = Bs[nr + kc];
                bf[j][1] = Bs[nr + kc + 4];
            }
            #pragma unroll
            for (int i = 0; i < 4; i++)
                #pragma unroll
                for (int j = 0; j < 4; j++)
                    mma_tf32(acc[i][j], af[i], bf[j]);
        }

        if (it + 1 < nk) {
            // store prefetched tile -> other stage (safe: last readers synced)
            uint32_t* Ad = sm4 + ((it + 1) & 1) * 2 * GSTAGEW;
            uint32_t* Bd = Ad + GSTAGEW;
            #pragma unroll
            for (int j = 0; j < 4; j++) {
                int id = tid + j * 256; int r = id >> 3; int c4 = (id & 7) * 4;
                *(uint4*)(Ad + r * GSTRIDE + c4) =
                    make_uint4(f2tf32(pa[j].x), f2tf32(pa[j].y), f2tf32(pa[j].z), f2tf32(pa[j].w));
                *(uint4*)(Bd + r * GSTRIDE + c4) =
                    make_uint4(f2tf32(pb[j].x), f2tf32(pb[j].y), f2tf32(pb[j].z), f2tf32(pb[j].w));
            }
            if (it + 2 < nk) {
                int kb = (it + 2) * 32;
                #pragma unroll
                for (int j = 0; j < 4; j++) {
                    int id = tid + j * 256; int r = id >> 3; int c4 = (id & 7) * 4;
                    pa[j] = *(const float4*)(Ab + (size_t)r * K + kb + c4);
                    pb[j] = *(const float4*)(Bb + (size_t)r * K + kb + c4);
                }
            }
            __syncthreads();
        }
    }

    // ---- epilogue: direct stores (float2 per fragment row) ----
    #pragma unroll
    for (int i = 0; i < 4; i++) {
        #pragma unroll
        for (int j = 0; j < 4; j++) {
            int rm = m0 + am + i * 16 + gr;
            int cn = n0 + bn + j * 8 + 2 * tg;
            #pragma unroll
            for (int half = 0; half < 2; half++) {
                int row = rm + half * 8;
                float v0 = acc[i][j][half * 2 + 0];
                float v1 = acc[i][j][half * 2 + 1];
                if (bias) { v0 += bias[cn]; v1 += bias[cn + 1]; }
                if (gvec) {
                    const float* gv = gvec + (row >> 11) * 6144 + goff + cn;
                    const float* rr = res + (size_t)row * N + cn;
                    v0 = rr[0] + gv[0] * v0;
                    v1 = rr[1] + gv[1] * v1;
                }
                *(float2*)(C + (size_t)row * N + cn) = make_float2(v0, v1);
            }
        }
    }
}

// ---------------------------------------------------------------------------
// adaLN GEMV
// ---------------------------------------------------------------------------
__global__ void __launch_bounds__(256) ada_kernel(
    const float* __restrict__ cond, const float* __restrict__ W,
    const float* __restrict__ bias, float* __restrict__ ada)
{
    __shared__ float sc[2048];
    int tid = threadIdx.x;
    for (int i = tid; i < 2048; i += 256) {
        float c = cond[i];
        sc[i] = c / (1.0f + expf(-c));
    }
    __syncthreads();
    int warp = blockIdx.x * 8 + (tid >> 5);
    int lane = tid & 31;
    int b = warp / 6144;
    int col = warp % 6144;
    const float* wr = W + (size_t)col * 1024;
    const float* cr = sc + b * 1024;
    float acc = 0.0f;
    #pragma unroll
    for (int i = 0; i < 8; i++) {
        int k = lane * 4 + i * 128;
        float4 wv = *(const float4*)(wr + k);
        acc += cr[k] * wv.x + cr[k + 1] * wv.y + cr[k + 2] * wv.z + cr[k + 3] * wv.w;
    }
    #pragma unroll
    for (int o = 16; o; o >>= 1) acc += __shfl_xor_sync(0xffffffffu, acc, o);
    if (lane == 0) ada[warp] = acc + bias[col];
}

// ---------------------------------------------------------------------------
// RMSNorm + modulate
// ---------------------------------------------------------------------------
__global__ void __launch_bounds__(256) norm_mod_kernel(
    const float* __restrict__ x, float* __restrict__ out,
    const float* __restrict__ w, const float* __restrict__ ada,
    int sh_off, int sc_off)
{
    int row = blockIdx.x;
    int b = row >> 11;
    int tid = threadIdx.x;
    const float* xr = x + (size_t)row * 1024;
    float4 v = *(const float4*)(xr + tid * 4);
    float ss = v.x * v.x + v.y * v.y + v.z * v.z + v.w * v.w;
    #pragma unroll
    for (int o = 16; o; o >>= 1) ss += __shfl_xor_sync(0xffffffffu, ss, o);
    __shared__ float red[8];
    if ((tid & 31) == 0) red[tid >> 5] = ss;
    __syncthreads();
    float tot = 0.0f;
    #pragma unroll
    for (int i = 0; i < 8; i++) tot += red[i];
    float inv = rsqrtf(tot * (1.0f / 1024.0f) + 1e-6f);
    const float* sh = ada + b * 6144 + sh_off;
    const float* sc = ada + b * 6144 + sc_off;
    int d = tid * 4;
    float4 o4;
    o4.x = v.x * inv * w[d]     * (1.0f + sc[d])     + sh[d];
    o4.y = v.y * inv * w[d + 1] * (1.0f + sc[d + 1]) + sh[d + 1];
    o4.z = v.z * inv * w[d + 2] * (1.0f + sc[d + 2]) + sh[d + 2];
    o4.w = v.w * inv * w[d + 3] * (1.0f + sc[d + 3]) + sh[d + 3];
    *(float4*)(out + (size_t)row * 1024 + d) = o4;
}

// ---------------------------------------------------------------------------
// QK RMSNorm + RoPE + transpose
// ---------------------------------------------------------------------------
__global__ void __launch_bounds__(256) qkv_post_kernel(
    const float* __restrict__ qkv, float* __restrict__ q, float* __restrict__ k,
    float* __restrict__ v, const float* __restrict__ qw,
    const float* __restrict__ kw, const int* __restrict__ widthp)
{
    int width = *widthp;
    int gw = blockIdx.x * 8 + (threadIdx.x >> 5);
    int lane = threadIdx.x & 31;
    int nh = gw & 15;
    int t  = (gw >> 4) & 2047;
    int b  = gw >> 15;
    const float* src = qkv + (size_t)(b * 2048 + t) * 3072;
    int hd0 = 2 * lane;

    float2 qv = *(const float2*)(src + nh * 64 + hd0);
    float2 kv = *(const float2*)(src + 1024 + nh * 64 + hd0);
    float2 vv = *(const float2*)(src + 2048 + nh * 64 + hd0);

    float ssq = qv.x * qv.x + qv.y * qv.y;
    float ssk = kv.x * kv.x + kv.y * kv.y;
    #pragma unroll
    for (int o = 16; o; o >>= 1) {
        ssq += __shfl_xor_sync(0xffffffffu, ssq, o);
        ssk += __shfl_xor_sync(0xffffffffu, ssk, o);
    }
    float qi = rsqrtf(ssq * (1.0f / 64.0f) + 1e-6f);
    float ki = rsqrtf(ssk * (1.0f / 64.0f) + 1e-6f);
    float qx = qv.x * qi * qw[hd0], qy = qv.y * qi * qw[hd0 + 1];
    float kx = kv.x * ki * kw[hd0], ky = kv.y * ki * kw[hd0 + 1];

    int yy = t / width, xx = t % width;
    int j = lane & 15;
    float coord = (float)((lane < 16) ? yy : xx);
    float freq = powf(10000.0f, -(float)j * (1.0f / 16.0f));
    float ang = coord * freq;
    float s, c;
    sincosf(ang, &s, &c);
    float qox = qx * c - qy * s;
    float qoy = qy * c + qx * s;
    float kox = kx * c - ky * s;
    float koy = ky * c + kx * s;

    size_t base = ((size_t)((b * 16 + nh) * 2048 + t)) * 64 + hd0;
    *(float2*)(q + base) = make_float2(qox, qoy);
    *(float2*)(k + base) = make_float2(kox, koy);
    *(float2*)(v + base) = make_float2(vv.x, vv.y);
}

// ---------------------------------------------------------------------------
// FP32 flash attention
// ---------------------------------------------------------------------------
#define ATT_STRIDE 68
__global__ void __launch_bounds__(256) attn_kernel(
    const float* __restrict__ Q, const float* __restrict__ K,
    const float* __restrict__ V, float* __restrict__ O)
{
    extern __shared__ float sm[];
    float* qs = sm;
    float* ks = sm + 64 * ATT_STRIDE;
    float* vs = sm + 2 * 64 * ATT_STRIDE;
    float* ps = sm + 3 * 64 * ATT_STRIDE;

    int tid = threadIdx.x;
    int tx = tid & 15, ty = tid >> 4;
    int qt = blockIdx.x, h = blockIdx.y, b = blockIdx.z;
    const size_t bh = ((size_t)(b * 16 + h)) * 2048 * 64;

    #pragma unroll
    for (int i = 0; i < 4; i++) {
        int f = tid + i * 256;
        int r = f >> 4, d0 = (f & 15) * 4;
        float4 qv = *(const float4*)(Q + bh + (size_t)(qt * 64 + r) * 64 + d0);
        qs[(d0 + 0) * ATT_STRIDE + r] = qv.x * 0.125f;
        qs[(d0 + 1) * ATT_STRIDE + r] = qv.y * 0.125f;
        qs[(d0 + 2) * ATT_STRIDE + r] = qv.z * 0.125f;
        qs[(d0 + 3) * ATT_STRIDE + r] = qv.w * 0.125f;
    }

    float m[4], l[4], acc[4][4];
    #pragma unroll
    for (int i = 0; i < 4; i++) {
        m[i] = -1e30f; l[i] = 0.0f;
        #pragma unroll
        for (int jj = 0; jj < 4; jj++) acc[i][jj] = 0.0f;
    }

    for (int kt = 0; kt < 32; kt++) {
        #pragma unroll
        for (int i = 0; i < 4; i++) {
            int f = tid + i * 256;
            int r = f >> 4, d0 = (f & 15) * 4;
            float4 kv = *(const float4*)(K + bh + (size_t)(kt * 64 + r) * 64 + d0);
            ks[(d0 + 0) * ATT_STRIDE + r] = kv.x;
            ks[(d0 + 1) * ATT_STRIDE + r] = kv.y;
            ks[(d0 + 2) * ATT_STRIDE + r] = kv.z;
            ks[(d0 + 3) * ATT_STRIDE + r] = kv.w;
            float4 vv = *(const float4*)(V + bh + (size_t)(kt * 64 + r) * 64 + d0);
            *(float4*)&vs[r * ATT_STRIDE + d0] = vv;
        }
        __syncthreads();

        float s[4][4];
        #pragma unroll
        for (int i = 0; i < 4; i++)
            #pragma unroll
            for (int jj = 0; jj < 4; jj++) s[i][jj] = 0.0f;
        #pragma unroll 8
        for (int d = 0; d < 64; d++) {
            float4 a  = *(const float4*)&qs[d * ATT_STRIDE + 4 * ty];
            float4 bk = *(const float4*)&ks[d * ATT_STRIDE + 4 * tx];
            float av[4] = {a.x, a.y, a.z, a.w};
            float bv[4] = {bk.x, bk.y, bk.z, bk.w};
            #pragma unroll
            for (int i = 0; i < 4; i++)
                #pragma unroll
                for (int jj = 0; jj < 4; jj++)
                    s[i][jj] += av[i] * bv[jj];
        }

        #pragma unroll
        for (int i = 0; i < 4; i++) {
            float rm = fmaxf(fmaxf(s[i][0], s[i][1]), fmaxf(s[i][2], s[i][3]));
            #pragma unroll
            for (int o = 8; o; o >>= 1) rm = fmaxf(rm, __shfl_xor_sync(0xffffffffu, rm, o));
            float mn = fmaxf(m[i], rm);
            float corr = __expf(m[i] - mn);
            float rsum = 0.0f;
            #pragma unroll
            for (int jj = 0; jj < 4; jj++) {
                s[i][jj] = __expf(s[i][jj] - mn);
                rsum += s[i][jj];
            }
            #pragma unroll
            for (int o = 8; o; o >>= 1) rsum += __shfl_xor_sync(0xffffffffu, rsum, o);
            l[i] = l[i] * corr + rsum;
            m[i] = mn;
            #pragma unroll
            for (int jj = 0; jj < 4; jj++) {
                acc[i][jj] *= corr;
                ps[(4 * tx + jj) * ATT_STRIDE + 4 * ty + i] = s[i][jj];
            }
        }
        __syncthreads();

        #pragma unroll 8
        for (int jk = 0; jk < 64; jk++) {
            float4 pv = *(const float4*)&ps[jk * ATT_STRIDE + 4 * ty];
            float4 vv = *(const float4*)&vs[jk * ATT_STRIDE + 4 * tx];
            float pa[4] = {pv.x, pv.y, pv.z, pv.w};
            float va[4] = {vv.x, vv.y, vv.z, vv.w};
            #pragma unroll
            for (int i = 0; i < 4; i++)
                #pragma unroll
                for (int jj = 0; jj < 4; jj++)
                    acc[i][jj] += pa[i] * va[jj];
        }
        __syncthreads();
    }

    #pragma unroll
    for (int i = 0; i < 4; i++) {
        float invl = 1.0f / l[i];
        int t = qt * 64 + 4 * ty + i;
        #pragma unroll
        for (int jj = 0; jj < 4; jj++) {
            O[(size_t)(b * 2048 + t) * 1024 + h * 64 + 4 * tx + jj] = acc[i][jj] * invl;
        }
    }
}

// ---------------------------------------------------------------------------
// MLP activation
// ---------------------------------------------------------------------------
__global__ void __launch_bounds__(256) mlp_act_kernel(
    const float* __restrict__ fc1, float* __restrict__ mid)
{
    int f = blockIdx.x * 256 + threadIdx.x;
    int row = f >> 10;
    int jcol = (f & 1023) * 4;
    float4 v = *(const float4*)(fc1 + (size_t)row * 8192 + jcol);
    float4 g = *(const float4*)(fc1 + (size_t)row * 8192 + 4096 + jcol);
    float4 o;
    o.x = v.x * g.x / (1.0f + __expf(-g.x));
    o.y = v.y * g.y / (1.0f + __expf(-g.y));
    o.z = v.z * g.z / (1.0f + __expf(-g.z));
    o.w = v.w * g.w / (1.0f + __expf(-g.w));
    *(float4*)(mid + (size_t)row * 4096 + jcol) = o;
}

// ---------------------------------------------------------------------------
// Launch
// ---------------------------------------------------------------------------
extern "C" void kernel_launch(void* const* d_in, const int* in_sizes, int n_in,
                              void* d_out, int out_size)
{
    const float* x        = (const float*)d_in[0];
    const float* cond     = (const float*)d_in[1];
    const float* norm1_w  = (const float*)d_in[2];
    const float* qkv_w    = (const float*)d_in[3];
    const float* q_norm_w = (const float*)d_in[4];
    const float* k_norm_w = (const float*)d_in[5];
    const float* proj_w   = (const float*)d_in[6];
    const float* proj_b   = (const float*)d_in[7];
    const float* norm2_w  = (const float*)d_in[8];
    const float* fc1_w    = (const float*)d_in[9];
    const float* fc1_b    = (const float*)d_in[10];
    const float* fc2_w    = (const float*)d_in[11];
    const float* fc2_b    = (const float*)d_in[12];
    const float* ada_w    = (const float*)d_in[13];
    const float* ada_b    = (const float*)d_in[14];
    const int*   widthp   = (const int*)d_in[16];
    float* out = (float*)d_out;

    float *p_ada, *p_h, *p_qkv, *p_q, *p_k, *p_v, *p_attn, *p_xa, *p_h2, *p_fc1, *p_mid;
    cudaGetSymbolAddress((void**)&p_ada, g_ada);
    cudaGetSymbolAddress((void**)&p_h, g_h);
    cudaGetSymbolAddress((void**)&p_qkv, g_qkv);
    cudaGetSymbolAddress((void**)&p_q, g_q);
    cudaGetSymbolAddress((void**)&p_k, g_k);
    cudaGetSymbolAddress((void**)&p_v, g_v);
    cudaGetSymbolAddress((void**)&p_attn, g_attn);
    cudaGetSymbolAddress((void**)&p_xa, g_xa);
    cudaGetSymbolAddress((void**)&p_h2, g_h2);
    cudaGetSymbolAddress((void**)&p_fc1, g_fc1);
    cudaGetSymbolAddress((void**)&p_mid, g_mid);

    int attn_smem = 4 * 64 * ATT_STRIDE * (int)sizeof(float);
    cudaFuncSetAttribute(attn_kernel, cudaFuncAttributeMaxDynamicSharedMemorySize, attn_smem);
    cudaFuncSetAttribute(gemm_mma, cudaFuncAttributeMaxDynamicSharedMemorySize, GT_DSMEM);

    // 1) adaLN
    ada_kernel<<<1536, 256>>>(cond, ada_w, ada_b, p_ada);
    // 2) norm1 + modulate
    norm_mod_kernel<<<4096, 256>>>(x, p_h, norm1_w, p_ada, 0, 1024);
    // 3) QKV GEMM (tf32 mma.sync)
    gemm_mma<<<dim3(3072 / 128, 4096 / 128), 256, GT_DSMEM>>>(p_h, qkv_w, p_qkv,
        4096, 3072, 1024, nullptr, nullptr, nullptr, 0);
    // 4) QK norm + RoPE + transpose
    qkv_post_kernel<<<8192, 256>>>(p_qkv, p_q, p_k, p_v, q_norm_w, k_norm_w, widthp);
    // 5) attention (fp32)
    attn_kernel<<<dim3(32, 16, 2), 256, attn_smem>>>(p_q, p_k, p_v, p_attn);
    // 6) proj GEMM + residual + gate
    gemm_mma<<<dim3(1024 / 128, 4096 / 128), 256, GT_DSMEM>>>(p_attn, proj_w, p_xa,
        4096, 1024, 1024, proj_b, x, p_ada, 2 * 1024);
    // 7) norm2 + modulate
    norm_mod_kernel<<<4096, 256>>>(p_xa, p_h2, norm2_w, p_ada, 3 * 1024, 4 * 1024);
    // 8) fc1 GEMM
    gemm_mma<<<dim3(8192 / 128, 4096 / 128), 256, GT_DSMEM>>>(p_h2, fc1_w, p_fc1,
        4096, 8192, 1024, fc1_b, nullptr, nullptr, 0);
    // 9) value * silu(gate)
    mlp_act_kernel<<<16384, 256>>>(p_fc1, p_mid);
    // 10) fc2 GEMM + residual + gate -> out
    gemm_mma<<<dim3(1024 / 128, 4096 / 128), 256, GT_DSMEM>>>(p_mid, fc2_w, out,
        4096, 1024, 4096, fc2_b, p_xa, p_ada, 5 * 1024);
}

// round 4
// speedup vs baseline: 2.8057x; 1.4587x over previous
#include <cuda_runtime.h>
#include <cuda_bf16.h>
#include <cstdint>
#include <cstddef>

// ---------------------------------------------------------------------------
// Problem constants: B=2, T=2048, D=1024, NH=16, HD=64, HID=4096, CD=1024
// ---------------------------------------------------------------------------
#define BT 4096
#define DD 1024
#define HID 4096

// ---------------------------------------------------------------------------
// Device scratch
// ---------------------------------------------------------------------------
__device__ float g_ada [2 * 6144];
__device__ float g_h   [(size_t)BT * DD];
__device__ float g_qkv [(size_t)BT * 3 * DD];
__device__ float g_q   [(size_t)BT * DD];
__device__ float g_k   [(size_t)BT * DD];
__device__ float g_v   [(size_t)BT * DD];
__device__ float g_attn[(size_t)BT * DD];
__device__ float g_xa  [(size_t)BT * DD];
__device__ float g_h2  [(size_t)BT * DD];
__device__ float g_fc1 [(size_t)BT * 2 * HID];
__device__ float g_mid [(size_t)BT * HID];

// ---------------------------------------------------------------------------
// tf32 helpers (base PTX only)
// ---------------------------------------------------------------------------
__device__ __forceinline__ uint32_t f2tf32(float x) {
    uint32_t u;
    asm("cvt.rna.tf32.f32 %0, %1;" : "=r"(u) : "f"(x));
    return u;
}
__device__ __forceinline__ void mma_tf32(float* c, const uint32_t* a, const uint32_t* b) {
    asm volatile(
        "mma.sync.aligned.m16n8k8.row.col.f32.tf32.tf32.f32 "
        "{%0,%1,%2,%3}, {%4,%5,%6,%7}, {%8,%9}, {%0,%1,%2,%3};"
        : "+f"(c[0]), "+f"(c[1]), "+f"(c[2]), "+f"(c[3])
        : "r"(a[0]), "r"(a[1]), "r"(a[2]), "r"(a[3]), "r"(b[0]), "r"(b[1]));
}

// ---------------------------------------------------------------------------
// TF32 tensor-core GEMM (unchanged from round 3)
// ---------------------------------------------------------------------------
#define GSTRIDE 36
#define GSTAGEW (128 * GSTRIDE)
#define GT_DSMEM (4 * GSTAGEW * 4)
__global__ void __launch_bounds__(256) gemm_mma(
    const float* __restrict__ A, const float* __restrict__ Bw,
    float* __restrict__ C, int M, int N, int K,
    const float* __restrict__ bias, const float* __restrict__ res,
    const float* __restrict__ gvec, int goff)
{
    extern __shared__ uint32_t sm4[];
    int tid = threadIdx.x;
    int wid = tid >> 5, lane = tid & 31;
    int gr = lane >> 2, tg = lane & 3;
    int wm = wid >> 2, wn = wid & 3;
    int m0 = blockIdx.y * 128, n0 = blockIdx.x * 128;

    const float* Ab = A + (size_t)m0 * K;
    const float* Bb = Bw + (size_t)n0 * K;
    const int nk = K >> 5;

    float acc[4][4][4];
    #pragma unroll
    for (int i = 0; i < 4; i++)
        #pragma unroll
        for (int j = 0; j < 4; j++)
            #pragma unroll
            for (int r = 0; r < 4; r++) acc[i][j][r] = 0.0f;

    float4 pa[4], pb[4];

    #pragma unroll
    for (int j = 0; j < 4; j++) {
        int id = tid + j * 256; int r = id >> 3; int c4 = (id & 7) * 4;
        pa[j] = *(const float4*)(Ab + (size_t)r * K + c4);
        pb[j] = *(const float4*)(Bb + (size_t)r * K + c4);
    }
    {
        uint32_t* As = sm4;
        uint32_t* Bs = sm4 + GSTAGEW;
        #pragma unroll
        for (int j = 0; j < 4; j++) {
            int id = tid + j * 256; int r = id >> 3; int c4 = (id & 7) * 4;
            *(uint4*)(As + r * GSTRIDE + c4) =
                make_uint4(f2tf32(pa[j].x), f2tf32(pa[j].y), f2tf32(pa[j].z), f2tf32(pa[j].w));
            *(uint4*)(Bs + r * GSTRIDE + c4) =
                make_uint4(f2tf32(pb[j].x), f2tf32(pb[j].y), f2tf32(pb[j].z), f2tf32(pb[j].w));
        }
    }
    if (nk > 1) {
        #pragma unroll
        for (int j = 0; j < 4; j++) {
            int id = tid + j * 256; int r = id >> 3; int c4 = (id & 7) * 4;
            pa[j] = *(const float4*)(Ab + (size_t)r * K + 32 + c4);
            pb[j] = *(const float4*)(Bb + (size_t)r * K + 32 + c4);
        }
    }
    __syncthreads();

    int am = wm * 64;
    int bn = wn * 32;

    for (int it = 0; it < nk; it++) {
        int s = it & 1;
        const uint32_t* As = sm4 + s * 2 * GSTAGEW;
        const uint32_t* Bs = As + GSTAGEW;

        #pragma unroll
        for (int ks = 0; ks < 4; ks++) {
            int kc = ks * 8 + tg;
            uint32_t af[4][4], bf[4][2];
            #pragma unroll
            for (int i = 0; i < 4; i++) {
                int mr = (am + i * 16 + gr) * GSTRIDE;
                af[i][0] = As[mr + kc];
                af[i][1] = As[mr + 8 * GSTRIDE + kc];
                af[i][2] = As[mr + kc + 4];
                af[i][3] = As[mr + 8 * GSTRIDE + kc + 4];
            }
            #pragma unroll
            for (int j = 0; j < 4; j++) {
                int nr = (bn + j * 8 + gr) * GSTRIDE;
                bf[j][0] = Bs[nr + kc];
                bf[j][1] = Bs[nr + kc + 4];
            }
            #pragma unroll
            for (int i = 0; i < 4; i++)
                #pragma unroll
                for (int j = 0; j < 4; j++)
                    mma_tf32(acc[i][j], af[i], bf[j]);
        }

        if (it + 1 < nk) {
            uint32_t* Ad = sm4 + ((it + 1) & 1) * 2 * GSTAGEW;
            uint32_t* Bd = Ad + GSTAGEW;
            #pragma unroll
            for (int j = 0; j < 4; j++) {
                int id = tid + j * 256; int r = id >> 3; int c4 = (id & 7) * 4;
                *(uint4*)(Ad + r * GSTRIDE + c4) =
                    make_uint4(f2tf32(pa[j].x), f2tf32(pa[j].y), f2tf32(pa[j].z), f2tf32(pa[j].w));
                *(uint4*)(Bd + r * GSTRIDE + c4) =
                    make_uint4(f2tf32(pb[j].x), f2tf32(pb[j].y), f2tf32(pb[j].z), f2tf32(pb[j].w));
            }
            if (it + 2 < nk) {
                int kb = (it + 2) * 32;
                #pragma unroll
                for (int j = 0; j < 4; j++) {
                    int id = tid + j * 256; int r = id >> 3; int c4 = (id & 7) * 4;
                    pa[j] = *(const float4*)(Ab + (size_t)r * K + kb + c4);
                    pb[j] = *(const float4*)(Bb + (size_t)r * K + kb + c4);
                }
            }
            __syncthreads();
        }
    }

    #pragma unroll
    for (int i = 0; i < 4; i++) {
        #pragma unroll
        for (int j = 0; j < 4; j++) {
            int rm = m0 + am + i * 16 + gr;
            int cn = n0 + bn + j * 8 + 2 * tg;
            #pragma unroll
            for (int half = 0; half < 2; half++) {
                int row = rm + half * 8;
                float v0 = acc[i][j][half * 2 + 0];
                float v1 = acc[i][j][half * 2 + 1];
                if (bias) { v0 += bias[cn]; v1 += bias[cn + 1]; }
                if (gvec) {
                    const float* gv = gvec + (row >> 11) * 6144 + goff + cn;
                    const float* rr = res + (size_t)row * N + cn;
                    v0 = rr[0] + gv[0] * v0;
                    v1 = rr[1] + gv[1] * v1;
                }
                *(float2*)(C + (size_t)row * N + cn) = make_float2(v0, v1);
            }
        }
    }
}

// ---------------------------------------------------------------------------
// adaLN GEMV
// ---------------------------------------------------------------------------
__global__ void __launch_bounds__(256) ada_kernel(
    const float* __restrict__ cond, const float* __restrict__ W,
    const float* __restrict__ bias, float* __restrict__ ada)
{
    __shared__ float sc[2048];
    int tid = threadIdx.x;
    for (int i = tid; i < 2048; i += 256) {
        float c = cond[i];
        sc[i] = c / (1.0f + expf(-c));
    }
    __syncthreads();
    int warp = blockIdx.x * 8 + (tid >> 5);
    int lane = tid & 31;
    int b = warp / 6144;
    int col = warp % 6144;
    const float* wr = W + (size_t)col * 1024;
    const float* cr = sc + b * 1024;
    float acc = 0.0f;
    #pragma unroll
    for (int i = 0; i < 8; i++) {
        int k = lane * 4 + i * 128;
        float4 wv = *(const float4*)(wr + k);
        acc += cr[k] * wv.x + cr[k + 1] * wv.y + cr[k + 2] * wv.z + cr[k + 3] * wv.w;
    }
    #pragma unroll
    for (int o = 16; o; o >>= 1) acc += __shfl_xor_sync(0xffffffffu, acc, o);
    if (lane == 0) ada[warp] = acc + bias[col];
}

// ---------------------------------------------------------------------------
// RMSNorm + modulate
// ---------------------------------------------------------------------------
__global__ void __launch_bounds__(256) norm_mod_kernel(
    const float* __restrict__ x, float* __restrict__ out,
    const float* __restrict__ w, const float* __restrict__ ada,
    int sh_off, int sc_off)
{
    int row = blockIdx.x;
    int b = row >> 11;
    int tid = threadIdx.x;
    const float* xr = x + (size_t)row * 1024;
    float4 v = *(const float4*)(xr + tid * 4);
    float ss = v.x * v.x + v.y * v.y + v.z * v.z + v.w * v.w;
    #pragma unroll
    for (int o = 16; o; o >>= 1) ss += __shfl_xor_sync(0xffffffffu, ss, o);
    __shared__ float red[8];
    if ((tid & 31) == 0) red[tid >> 5] = ss;
    __syncthreads();
    float tot = 0.0f;
    #pragma unroll
    for (int i = 0; i < 8; i++) tot += red[i];
    float inv = rsqrtf(tot * (1.0f / 1024.0f) + 1e-6f);
    const float* sh = ada + b * 6144 + sh_off;
    const float* sc = ada + b * 6144 + sc_off;
    int d = tid * 4;
    float4 o4;
    o4.x = v.x * inv * w[d]     * (1.0f + sc[d])     + sh[d];
    o4.y = v.y * inv * w[d + 1] * (1.0f + sc[d + 1]) + sh[d + 1];
    o4.z = v.z * inv * w[d + 2] * (1.0f + sc[d + 2]) + sh[d + 2];
    o4.w = v.w * inv * w[d + 3] * (1.0f + sc[d + 3]) + sh[d + 3];
    *(float4*)(out + (size_t)row * 1024 + d) = o4;
}

// ---------------------------------------------------------------------------
// QK RMSNorm + RoPE + transpose
// ---------------------------------------------------------------------------
__global__ void __launch_bounds__(256) qkv_post_kernel(
    const float* __restrict__ qkv, float* __restrict__ q, float* __restrict__ k,
    float* __restrict__ v, const float* __restrict__ qw,
    const float* __restrict__ kw, const int* __restrict__ widthp)
{
    int width = *widthp;
    int gw = blockIdx.x * 8 + (threadIdx.x >> 5);
    int lane = threadIdx.x & 31;
    int nh = gw & 15;
    int t  = (gw >> 4) & 2047;
    int b  = gw >> 15;
    const float* src = qkv + (size_t)(b * 2048 + t) * 3072;
    int hd0 = 2 * lane;

    float2 qv = *(const float2*)(src + nh * 64 + hd0);
    float2 kv = *(const float2*)(src + 1024 + nh * 64 + hd0);
    float2 vv = *(const float2*)(src + 2048 + nh * 64 + hd0);

    float ssq = qv.x * qv.x + qv.y * qv.y;
    float ssk = kv.x * kv.x + kv.y * kv.y;
    #pragma unroll
    for (int o = 16; o; o >>= 1) {
        ssq += __shfl_xor_sync(0xffffffffu, ssq, o);
        ssk += __shfl_xor_sync(0xffffffffu, ssk, o);
    }
    float qi = rsqrtf(ssq * (1.0f / 64.0f) + 1e-6f);
    float ki = rsqrtf(ssk * (1.0f / 64.0f) + 1e-6f);
    float qx = qv.x * qi * qw[hd0], qy = qv.y * qi * qw[hd0 + 1];
    float kx = kv.x * ki * kw[hd0], ky = kv.y * ki * kw[hd0 + 1];

    int yy = t / width, xx = t % width;
    int j = lane & 15;
    float coord = (float)((lane < 16) ? yy : xx);
    float freq = powf(10000.0f, -(float)j * (1.0f / 16.0f));
    float ang = coord * freq;
    float s, c;
    sincosf(ang, &s, &c);
    float qox = qx * c - qy * s;
    float qoy = qy * c + qx * s;
    float kox = kx * c - ky * s;
    float koy = ky * c + kx * s;

    size_t base = ((size_t)((b * 16 + nh) * 2048 + t)) * 64 + hd0;
    *(float2*)(q + base) = make_float2(qox, qoy);
    *(float2*)(k + base) = make_float2(kox, koy);
    *(float2*)(v + base) = make_float2(vv.x, vv.y);
}

// ---------------------------------------------------------------------------
// TF32 tensor-core flash attention.
// Block: one (b,h) x 128-query tile. 8 warps; each warp owns 16 rows.
// K chunk 64 keys. Q/K/P/Vt in SMEM (tf32), stride 68 words (68 mod 32 = 4).
// ---------------------------------------------------------------------------
#define ASTR 68
#define AQ_OFF   0
#define AK_OFF   (128 * ASTR)
#define AV_OFF   (AK_OFF + 64 * ASTR)
#define AP_OFF   (AV_OFF + 64 * ASTR)
#define ATT_SMEMW (AP_OFF + 128 * ASTR)
__global__ void __launch_bounds__(256) attn_mma_kernel(
    const float* __restrict__ Q, const float* __restrict__ K,
    const float* __restrict__ V, float* __restrict__ O)
{
    extern __shared__ uint32_t asm4[];
    int tid = threadIdx.x;
    int wid = tid >> 5, lane = tid & 31;
    int gr = lane >> 2, tg = lane & 3;
    int qt = blockIdx.x, h = blockIdx.y, b = blockIdx.z;
    const size_t bh = ((size_t)(b * 16 + h)) * 2048 * 64;

    // ---- load Q tile (scale 0.125 folded) -> SMEM tf32 [row][d], stride 68
    #pragma unroll
    for (int j = 0; j < 8; j++) {
        int id = tid + j * 256;
        int r = id >> 4, c4 = (id & 15) * 4;
        float4 qv = *(const float4*)(Q + bh + (size_t)(qt * 128 + r) * 64 + c4);
        *(uint4*)(asm4 + AQ_OFF + r * ASTR + c4) =
            make_uint4(f2tf32(qv.x * 0.125f), f2tf32(qv.y * 0.125f),
                       f2tf32(qv.z * 0.125f), f2tf32(qv.w * 0.125f));
    }

    // ---- prefetch chunk 0 K/V
    float4 pk[4], pv[4];
    #pragma unroll
    for (int j = 0; j < 4; j++) {
        int id = tid + j * 256;
        int r = id >> 4, c4 = (id & 15) * 4;
        pk[j] = *(const float4*)(K + bh + (size_t)r * 64 + c4);
        pv[j] = *(const float4*)(V + bh + (size_t)r * 64 + c4);
    }

    float m0 = -1e30f, m1 = -1e30f, l0 = 0.0f, l1 = 0.0f;
    float o[8][4];
    #pragma unroll
    for (int j = 0; j < 8; j++)
        #pragma unroll
        for (int r = 0; r < 4; r++) o[j][r] = 0.0f;

    const int wrow = wid * 16;

    for (int kt = 0; kt < 32; kt++) {
        __syncthreads();   // previous chunk's smem reads finished (also covers Q store)
        // store K chunk [key][d] and V transposed [d][key]
        #pragma unroll
        for (int j = 0; j < 4; j++) {
            int id = tid + j * 256;
            int r = id >> 4, c4 = (id & 15) * 4;
            *(uint4*)(asm4 + AK_OFF + r * ASTR + c4) =
                make_uint4(f2tf32(pk[j].x), f2tf32(pk[j].y), f2tf32(pk[j].z), f2tf32(pk[j].w));
            asm4[AV_OFF + (c4 + 0) * ASTR + r] = f2tf32(pv[j].x);
            asm4[AV_OFF + (c4 + 1) * ASTR + r] = f2tf32(pv[j].y);
            asm4[AV_OFF + (c4 + 2) * ASTR + r] = f2tf32(pv[j].z);
            asm4[AV_OFF + (c4 + 3) * ASTR + r] = f2tf32(pv[j].w);
        }
        __syncthreads();
        // prefetch next chunk
        if (kt + 1 < 32) {
            size_t kb = bh + (size_t)(kt + 1) * 64 * 64;
            #pragma unroll
            for (int j = 0; j < 4; j++) {
                int id = tid + j * 256;
                int r = id >> 4, c4 = (id & 15) * 4;
                pk[j] = *(const float4*)(K + kb + (size_t)r * 64 + c4);
                pv[j] = *(const float4*)(V + kb + (size_t)r * 64 + c4);
            }
        }

        // ---- S = Q K^T : warp rows [wrow, wrow+16), all 64 keys
        float s[8][4];
        #pragma unroll
        for (int j = 0; j < 8; j++)
            #pragma unroll
            for (int r = 0; r < 4; r++) s[j][r] = 0.0f;
        #pragma unroll
        for (int ks = 0; ks < 8; ks++) {
            int kc = ks * 8 + tg;
            uint32_t af[4], bf[8][2];
            int mr = (wrow + gr) * ASTR;
            af[0] = asm4[AQ_OFF + mr + kc];
            af[1] = asm4[AQ_OFF + mr + 8 * ASTR + kc];
            af[2] = asm4[AQ_OFF + mr + kc + 4];
            af[3] = asm4[AQ_OFF + mr + 8 * ASTR + kc + 4];
            #pragma unroll
            for (int j = 0; j < 8; j++) {
                int nr = (j * 8 + gr) * ASTR;
                bf[j][0] = asm4[AK_OFF + nr + kc];
                bf[j][1] = asm4[AK_OFF + nr + kc + 4];
            }
            #pragma unroll
            for (int j = 0; j < 8; j++)
                mma_tf32(s[j], af, bf[j]);
        }

        // ---- online softmax (rows gr and gr+8; reduce over 4 quad lanes)
        float mx0 = -1e30f, mx1 = -1e30f;
        #pragma unroll
        for (int j = 0; j < 8; j++) {
            mx0 = fmaxf(mx0, fmaxf(s[j][0], s[j][1]));
            mx1 = fmaxf(mx1, fmaxf(s[j][2], s[j][3]));
        }
        #pragma unroll
        for (int off = 1; off <= 2; off <<= 1) {
            mx0 = fmaxf(mx0, __shfl_xor_sync(0xffffffffu, mx0, off));
            mx1 = fmaxf(mx1, __shfl_xor_sync(0xffffffffu, mx1, off));
        }
        float mn0 = fmaxf(m0, mx0), mn1 = fmaxf(m1, mx1);
        float cr0 = __expf(m0 - mn0), cr1 = __expf(m1 - mn1);
        m0 = mn0; m1 = mn1;
        float sum0 = 0.0f, sum1 = 0.0f;
        #pragma unroll
        for (int j = 0; j < 8; j++) {
            float e00 = __expf(s[j][0] - mn0);
            float e01 = __expf(s[j][1] - mn0);
            float e10 = __expf(s[j][2] - mn1);
            float e11 = __expf(s[j][3] - mn1);
            sum0 += e00 + e01;
            sum1 += e10 + e11;
            int pc = j * 8 + 2 * tg;
            asm4[AP_OFF + (wrow + gr) * ASTR + pc]     = f2tf32(e00);
            asm4[AP_OFF + (wrow + gr) * ASTR + pc + 1] = f2tf32(e01);
            asm4[AP_OFF + (wrow + gr + 8) * ASTR + pc]     = f2tf32(e10);
            asm4[AP_OFF + (wrow + gr + 8) * ASTR + pc + 1] = f2tf32(e11);
        }
        #pragma unroll
        for (int off = 1; off <= 2; off <<= 1) {
            sum0 += __shfl_xor_sync(0xffffffffu, sum0, off);
            sum1 += __shfl_xor_sync(0xffffffffu, sum1, off);
        }
        l0 = l0 * cr0 + sum0;
        l1 = l1 * cr1 + sum1;
        #pragma unroll
        for (int j = 0; j < 8; j++) {
            o[j][0] *= cr0; o[j][1] *= cr0;
            o[j][2] *= cr1; o[j][3] *= cr1;
        }
        __syncwarp();

        // ---- O += P @ V  (A = P [row][key], B = Vt [d][key])
        #pragma unroll
        for (int ks = 0; ks < 8; ks++) {
            int kc = ks * 8 + tg;
            uint32_t af[4], bf[8][2];
            int mr = (wrow + gr) * ASTR;
            af[0] = asm4[AP_OFF + mr + kc];
            af[1] = asm4[AP_OFF + mr + 8 * ASTR + kc];
            af[2] = asm4[AP_OFF + mr + kc + 4];
            af[3] = asm4[AP_OFF + mr + 8 * ASTR + kc + 4];
            #pragma unroll
            for (int j = 0; j < 8; j++) {
                int nr = (j * 8 + gr) * ASTR;
                bf[j][0] = asm4[AV_OFF + nr + kc];
                bf[j][1] = asm4[AV_OFF + nr + kc + 4];
            }
            #pragma unroll
            for (int j = 0; j < 8; j++)
                mma_tf32(o[j], af, bf[j]);
        }
    }

    // ---- finalize and store: O[b*2048+t][h*64 + d]
    float inv0 = 1.0f / l0, inv1 = 1.0f / l1;
    int t0 = qt * 128 + wrow + gr;
    #pragma unroll
    for (int j = 0; j < 8; j++) {
        int cn = h * 64 + j * 8 + 2 * tg;
        *(float2*)(O + (size_t)(b * 2048 + t0) * 1024 + cn) =
            make_float2(o[j][0] * inv0, o[j][1] * inv0);
        *(float2*)(O + (size_t)(b * 2048 + t0 + 8) * 1024 + cn) =
            make_float2(o[j][2] * inv1, o[j][3] * inv1);
    }
}

// ---------------------------------------------------------------------------
// MLP activation
// ---------------------------------------------------------------------------
__global__ void __launch_bounds__(256) mlp_act_kernel(
    const float* __restrict__ fc1, float* __restrict__ mid)
{
    int f = blockIdx.x * 256 + threadIdx.x;
    int row = f >> 10;
    int jcol = (f & 1023) * 4;
    float4 v = *(const float4*)(fc1 + (size_t)row * 8192 + jcol);
    float4 g = *(const float4*)(fc1 + (size_t)row * 8192 + 4096 + jcol);
    float4 o;
    o.x = v.x * g.x / (1.0f + __expf(-g.x));
    o.y = v.y * g.y / (1.0f + __expf(-g.y));
    o.z = v.z * g.z / (1.0f + __expf(-g.z));
    o.w = v.w * g.w / (1.0f + __expf(-g.w));
    *(float4*)(mid + (size_t)row * 4096 + jcol) = o;
}

// ---------------------------------------------------------------------------
// Launch
// ---------------------------------------------------------------------------
extern "C" void kernel_launch(void* const* d_in, const int* in_sizes, int n_in,
                              void* d_out, int out_size)
{
    const float* x        = (const float*)d_in[0];
    const float* cond     = (const float*)d_in[1];
    const float* norm1_w  = (const float*)d_in[2];
    const float* qkv_w    = (const float*)d_in[3];
    const float* q_norm_w = (const float*)d_in[4];
    const float* k_norm_w = (const float*)d_in[5];
    const float* proj_w   = (const float*)d_in[6];
    const float* proj_b   = (const float*)d_in[7];
    const float* norm2_w  = (const float*)d_in[8];
    const float* fc1_w    = (const float*)d_in[9];
    const float* fc1_b    = (const float*)d_in[10];
    const float* fc2_w    = (const float*)d_in[11];
    const float* fc2_b    = (const float*)d_in[12];
    const float* ada_w    = (const float*)d_in[13];
    const float* ada_b    = (const float*)d_in[14];
    const int*   widthp   = (const int*)d_in[16];
    float* out = (float*)d_out;

    float *p_ada, *p_h, *p_qkv, *p_q, *p_k, *p_v, *p_attn, *p_xa, *p_h2, *p_fc1, *p_mid;
    cudaGetSymbolAddress((void**)&p_ada, g_ada);
    cudaGetSymbolAddress((void**)&p_h, g_h);
    cudaGetSymbolAddress((void**)&p_qkv, g_qkv);
    cudaGetSymbolAddress((void**)&p_q, g_q);
    cudaGetSymbolAddress((void**)&p_k, g_k);
    cudaGetSymbolAddress((void**)&p_v, g_v);
    cudaGetSymbolAddress((void**)&p_attn, g_attn);
    cudaGetSymbolAddress((void**)&p_xa, g_xa);
    cudaGetSymbolAddress((void**)&p_h2, g_h2);
    cudaGetSymbolAddress((void**)&p_fc1, g_fc1);
    cudaGetSymbolAddress((void**)&p_mid, g_mid);

    int attn_smem = ATT_SMEMW * 4;
    cudaFuncSetAttribute(attn_mma_kernel, cudaFuncAttributeMaxDynamicSharedMemorySize, attn_smem);
    cudaFuncSetAttribute(gemm_mma, cudaFuncAttributeMaxDynamicSharedMemorySize, GT_DSMEM);

    // 1) adaLN
    ada_kernel<<<1536, 256>>>(cond, ada_w, ada_b, p_ada);
    // 2) norm1 + modulate
    norm_mod_kernel<<<4096, 256>>>(x, p_h, norm1_w, p_ada, 0, 1024);
    // 3) QKV GEMM
    gemm_mma<<<dim3(3072 / 128, 4096 / 128), 256, GT_DSMEM>>>(p_h, qkv_w, p_qkv,
        4096, 3072, 1024, nullptr, nullptr, nullptr, 0);
    // 4) QK norm + RoPE + transpose
    qkv_post_kernel<<<8192, 256>>>(p_qkv, p_q, p_k, p_v, q_norm_w, k_norm_w, widthp);
    // 5) attention (tf32 mma)
    attn_mma_kernel<<<dim3(16, 16, 2), 256, attn_smem>>>(p_q, p_k, p_v, p_attn);
    // 6) proj GEMM + residual + gate
    gemm_mma<<<dim3(1024 / 128, 4096 / 128), 256, GT_DSMEM>>>(p_attn, proj_w, p_xa,
        4096, 1024, 1024, proj_b, x, p_ada, 2 * 1024);
    // 7) norm2 + modulate
    norm_mod_kernel<<<4096, 256>>>(p_xa, p_h2, norm2_w, p_ada, 3 * 1024, 4 * 1024);
    // 8) fc1 GEMM
    gemm_mma<<<dim3(8192 / 128, 4096 / 128), 256, GT_DSMEM>>>(p_h2, fc1_w, p_fc1,
        4096, 8192, 1024, fc1_b, nullptr, nullptr, 0);
    // 9) value * silu(gate)
    mlp_act_kernel<<<16384, 256>>>(p_fc1, p_mid);
    // 10) fc2 GEMM + residual + gate -> out
    gemm_mma<<<dim3(1024 / 128, 4096 / 128), 256, GT_DSMEM>>>(p_mid, fc2_w, out,
        4096, 1024, 4096, fc2_b, p_xa, p_ada, 5 * 1024);
}

// round 5
// speedup vs baseline: 2.9182x; 1.0401x over previous
#include <cuda_runtime.h>
#include <cuda_bf16.h>
#include <cstdint>
#include <cstddef>

// ---------------------------------------------------------------------------
// Problem constants: B=2, T=2048, D=1024, NH=16, HD=64, HID=4096, CD=1024
// ---------------------------------------------------------------------------
#define BT 4096
#define DD 1024
#define HID 4096

// ---------------------------------------------------------------------------
// Device scratch
// ---------------------------------------------------------------------------
__device__ float g_ada [2 * 6144];
__device__ float g_h   [(size_t)BT * DD];
__device__ float g_qkv [(size_t)BT * 3 * DD];
__device__ float g_q   [(size_t)BT * DD];
__device__ float g_k   [(size_t)BT * DD];
__device__ float g_v   [(size_t)BT * DD];
__device__ float g_attn[(size_t)BT * DD];
__device__ float g_xa  [(size_t)BT * DD];
__device__ float g_h2  [(size_t)BT * DD];
__device__ float g_fc1 [(size_t)BT * 2 * HID];
__device__ float g_mid [(size_t)BT * HID];

// ---------------------------------------------------------------------------
// tf32 helpers (base PTX only)
// ---------------------------------------------------------------------------
__device__ __forceinline__ uint32_t f2tf32(float x) {
    uint32_t u;
    asm("cvt.rna.tf32.f32 %0, %1;" : "=r"(u) : "f"(x));
    return u;
}
__device__ __forceinline__ void mma_tf32(float* c, const uint32_t* a, const uint32_t* b) {
    asm volatile(
        "mma.sync.aligned.m16n8k8.row.col.f32.tf32.tf32.f32 "
        "{%0,%1,%2,%3}, {%4,%5,%6,%7}, {%8,%9}, {%0,%1,%2,%3};"
        : "+f"(c[0]), "+f"(c[1]), "+f"(c[2]), "+f"(c[3])
        : "r"(a[0]), "r"(a[1]), "r"(a[2]), "r"(a[3]), "r"(b[0]), "r"(b[1]));
}

// ---------------------------------------------------------------------------
// TF32 tensor-core GEMM (unchanged — known good)
// ---------------------------------------------------------------------------
#define GSTRIDE 36
#define GSTAGEW (128 * GSTRIDE)
#define GT_DSMEM (4 * GSTAGEW * 4)
__global__ void __launch_bounds__(256) gemm_mma(
    const float* __restrict__ A, const float* __restrict__ Bw,
    float* __restrict__ C, int M, int N, int K,
    const float* __restrict__ bias, const float* __restrict__ res,
    const float* __restrict__ gvec, int goff)
{
    extern __shared__ uint32_t sm4[];
    int tid = threadIdx.x;
    int wid = tid >> 5, lane = tid & 31;
    int gr = lane >> 2, tg = lane & 3;
    int wm = wid >> 2, wn = wid & 3;
    int m0 = blockIdx.y * 128, n0 = blockIdx.x * 128;

    const float* Ab = A + (size_t)m0 * K;
    const float* Bb = Bw + (size_t)n0 * K;
    const int nk = K >> 5;

    float acc[4][4][4];
    #pragma unroll
    for (int i = 0; i < 4; i++)
        #pragma unroll
        for (int j = 0; j < 4; j++)
            #pragma unroll
            for (int r = 0; r < 4; r++) acc[i][j][r] = 0.0f;

    float4 pa[4], pb[4];

    #pragma unroll
    for (int j = 0; j < 4; j++) {
        int id = tid + j * 256; int r = id >> 3; int c4 = (id & 7) * 4;
        pa[j] = *(const float4*)(Ab + (size_t)r * K + c4);
        pb[j] = *(const float4*)(Bb + (size_t)r * K + c4);
    }
    {
        uint32_t* As = sm4;
        uint32_t* Bs = sm4 + GSTAGEW;
        #pragma unroll
        for (int j = 0; j < 4; j++) {
            int id = tid + j * 256; int r = id >> 3; int c4 = (id & 7) * 4;
            *(uint4*)(As + r * GSTRIDE + c4) =
                make_uint4(f2tf32(pa[j].x), f2tf32(pa[j].y), f2tf32(pa[j].z), f2tf32(pa[j].w));
            *(uint4*)(Bs + r * GSTRIDE + c4) =
                make_uint4(f2tf32(pb[j].x), f2tf32(pb[j].y), f2tf32(pb[j].z), f2tf32(pb[j].w));
        }
    }
    if (nk > 1) {
        #pragma unroll
        for (int j = 0; j < 4; j++) {
            int id = tid + j * 256; int r = id >> 3; int c4 = (id & 7) * 4;
            pa[j] = *(const float4*)(Ab + (size_t)r * K + 32 + c4);
            pb[j] = *(const float4*)(Bb + (size_t)r * K + 32 + c4);
        }
    }
    __syncthreads();

    int am = wm * 64;
    int bn = wn * 32;

    for (int it = 0; it < nk; it++) {
        int s = it & 1;
        const uint32_t* As = sm4 + s * 2 * GSTAGEW;
        const uint32_t* Bs = As + GSTAGEW;

        #pragma unroll
        for (int ks = 0; ks < 4; ks++) {
            int kc = ks * 8 + tg;
            uint32_t af[4][4], bf[4][2];
            #pragma unroll
            for (int i = 0; i < 4; i++) {
                int mr = (am + i * 16 + gr) * GSTRIDE;
                af[i][0] = As[mr + kc];
                af[i][1] = As[mr + 8 * GSTRIDE + kc];
                af[i][2] = As[mr + kc + 4];
                af[i][3] = As[mr + 8 * GSTRIDE + kc + 4];
            }
            #pragma unroll
            for (int j = 0; j < 4; j++) {
                int nr = (bn + j * 8 + gr) * GSTRIDE;
                bf[j][0] = Bs[nr + kc];
                bf[j][1] = Bs[nr + kc + 4];
            }
            #pragma unroll
            for (int i = 0; i < 4; i++)
                #pragma unroll
                for (int j = 0; j < 4; j++)
                    mma_tf32(acc[i][j], af[i], bf[j]);
        }

        if (it + 1 < nk) {
            uint32_t* Ad = sm4 + ((it + 1) & 1) * 2 * GSTAGEW;
            uint32_t* Bd = Ad + GSTAGEW;
            #pragma unroll
            for (int j = 0; j < 4; j++) {
                int id = tid + j * 256; int r = id >> 3; int c4 = (id & 7) * 4;
                *(uint4*)(Ad + r * GSTRIDE + c4) =
                    make_uint4(f2tf32(pa[j].x), f2tf32(pa[j].y), f2tf32(pa[j].z), f2tf32(pa[j].w));
                *(uint4*)(Bd + r * GSTRIDE + c4) =
                    make_uint4(f2tf32(pb[j].x), f2tf32(pb[j].y), f2tf32(pb[j].z), f2tf32(pb[j].w));
            }
            if (it + 2 < nk) {
                int kb = (it + 2) * 32;
                #pragma unroll
                for (int j = 0; j < 4; j++) {
                    int id = tid + j * 256; int r = id >> 3; int c4 = (id & 7) * 4;
                    pa[j] = *(const float4*)(Ab + (size_t)r * K + kb + c4);
                    pb[j] = *(const float4*)(Bb + (size_t)r * K + kb + c4);
                }
            }
            __syncthreads();
        }
    }

    #pragma unroll
    for (int i = 0; i < 4; i++) {
        #pragma unroll
        for (int j = 0; j < 4; j++) {
            int rm = m0 + am + i * 16 + gr;
            int cn = n0 + bn + j * 8 + 2 * tg;
            #pragma unroll
            for (int half = 0; half < 2; half++) {
                int row = rm + half * 8;
                float v0 = acc[i][j][half * 2 + 0];
                float v1 = acc[i][j][half * 2 + 1];
                if (bias) { v0 += bias[cn]; v1 += bias[cn + 1]; }
                if (gvec) {
                    const float* gv = gvec + (row >> 11) * 6144 + goff + cn;
                    const float* rr = res + (size_t)row * N + cn;
                    v0 = rr[0] + gv[0] * v0;
                    v1 = rr[1] + gv[1] * v1;
                }
                *(float2*)(C + (size_t)row * N + cn) = make_float2(v0, v1);
            }
        }
    }
}

// ---------------------------------------------------------------------------
// adaLN GEMV
// ---------------------------------------------------------------------------
__global__ void __launch_bounds__(256) ada_kernel(
    const float* __restrict__ cond, const float* __restrict__ W,
    const float* __restrict__ bias, float* __restrict__ ada)
{
    __shared__ float sc[2048];
    int tid = threadIdx.x;
    for (int i = tid; i < 2048; i += 256) {
        float c = cond[i];
        sc[i] = c / (1.0f + expf(-c));
    }
    __syncthreads();
    int warp = blockIdx.x * 8 + (tid >> 5);
    int lane = tid & 31;
    int b = warp / 6144;
    int col = warp % 6144;
    const float* wr = W + (size_t)col * 1024;
    const float* cr = sc + b * 1024;
    float acc = 0.0f;
    #pragma unroll
    for (int i = 0; i < 8; i++) {
        int k = lane * 4 + i * 128;
        float4 wv = *(const float4*)(wr + k);
        acc += cr[k] * wv.x + cr[k + 1] * wv.y + cr[k + 2] * wv.z + cr[k + 3] * wv.w;
    }
    #pragma unroll
    for (int o = 16; o; o >>= 1) acc += __shfl_xor_sync(0xffffffffu, acc, o);
    if (lane == 0) ada[warp] = acc + bias[col];
}

// ---------------------------------------------------------------------------
// RMSNorm + modulate
// ---------------------------------------------------------------------------
__global__ void __launch_bounds__(256) norm_mod_kernel(
    const float* __restrict__ x, float* __restrict__ out,
    const float* __restrict__ w, const float* __restrict__ ada,
    int sh_off, int sc_off)
{
    int row = blockIdx.x;
    int b = row >> 11;
    int tid = threadIdx.x;
    const float* xr = x + (size_t)row * 1024;
    float4 v = *(const float4*)(xr + tid * 4);
    float ss = v.x * v.x + v.y * v.y + v.z * v.z + v.w * v.w;
    #pragma unroll
    for (int o = 16; o; o >>= 1) ss += __shfl_xor_sync(0xffffffffu, ss, o);
    __shared__ float red[8];
    if ((tid & 31) == 0) red[tid >> 5] = ss;
    __syncthreads();
    float tot = 0.0f;
    #pragma unroll
    for (int i = 0; i < 8; i++) tot += red[i];
    float inv = rsqrtf(tot * (1.0f / 1024.0f) + 1e-6f);
    const float* sh = ada + b * 6144 + sh_off;
    const float* sc = ada + b * 6144 + sc_off;
    int d = tid * 4;
    float4 o4;
    o4.x = v.x * inv * w[d]     * (1.0f + sc[d])     + sh[d];
    o4.y = v.y * inv * w[d + 1] * (1.0f + sc[d + 1]) + sh[d + 1];
    o4.z = v.z * inv * w[d + 2] * (1.0f + sc[d + 2]) + sh[d + 2];
    o4.w = v.w * inv * w[d + 3] * (1.0f + sc[d + 3]) + sh[d + 3];
    *(float4*)(out + (size_t)row * 1024 + d) = o4;
}

// ---------------------------------------------------------------------------
// QK RMSNorm + RoPE + transpose
// ---------------------------------------------------------------------------
__global__ void __launch_bounds__(256) qkv_post_kernel(
    const float* __restrict__ qkv, float* __restrict__ q, float* __restrict__ k,
    float* __restrict__ v, const float* __restrict__ qw,
    const float* __restrict__ kw, const int* __restrict__ widthp)
{
    int width = *widthp;
    int gw = blockIdx.x * 8 + (threadIdx.x >> 5);
    int lane = threadIdx.x & 31;
    int nh = gw & 15;
    int t  = (gw >> 4) & 2047;
    int b  = gw >> 15;
    const float* src = qkv + (size_t)(b * 2048 + t) * 3072;
    int hd0 = 2 * lane;

    float2 qv = *(const float2*)(src + nh * 64 + hd0);
    float2 kv = *(const float2*)(src + 1024 + nh * 64 + hd0);
    float2 vv = *(const float2*)(src + 2048 + nh * 64 + hd0);

    float ssq = qv.x * qv.x + qv.y * qv.y;
    float ssk = kv.x * kv.x + kv.y * kv.y;
    #pragma unroll
    for (int o = 16; o; o >>= 1) {
        ssq += __shfl_xor_sync(0xffffffffu, ssq, o);
        ssk += __shfl_xor_sync(0xffffffffu, ssk, o);
    }
    float qi = rsqrtf(ssq * (1.0f / 64.0f) + 1e-6f);
    float ki = rsqrtf(ssk * (1.0f / 64.0f) + 1e-6f);
    float qx = qv.x * qi * qw[hd0], qy = qv.y * qi * qw[hd0 + 1];
    float kx = kv.x * ki * kw[hd0], ky = kv.y * ki * kw[hd0 + 1];

    int yy = t / width, xx = t % width;
    int j = lane & 15;
    float coord = (float)((lane < 16) ? yy : xx);
    float freq = powf(10000.0f, -(float)j * (1.0f / 16.0f));
    float ang = coord * freq;
    float s, c;
    sincosf(ang, &s, &c);
    float qox = qx * c - qy * s;
    float qoy = qy * c + qx * s;
    float kox = kx * c - ky * s;
    float koy = ky * c + kx * s;

    size_t base = ((size_t)((b * 16 + nh) * 2048 + t)) * 64 + hd0;
    *(float2*)(q + base) = make_float2(qox, qoy);
    *(float2*)(k + base) = make_float2(kox, koy);
    *(float2*)(v + base) = make_float2(vv.x, vv.y);
}

// ---------------------------------------------------------------------------
// TF32 tensor-core flash attention, v2.
// Block: one (b,h) x 256-query tile. 8 warps; each warp owns 32 rows
// (2 m16 fragments). K chunk 64 keys, double-buffered K/V stages ->
// ONE __syncthreads per chunk. Q/K/V/P in SMEM tf32, stride 68 words.
// ---------------------------------------------------------------------------
#define A2STR 68
#define A2Q   0
#define A2KV  (256 * A2STR)                 // 2 stages x (K 64 rows + Vt 64 rows)
#define A2KVS (128 * A2STR)                 // words per stage
#define A2P   (A2KV + 2 * A2KVS)
#define ATT2_SMEMW (A2P + 256 * A2STR)      // (256+256+256)*68 = 52224 words
__global__ void __launch_bounds__(256) attn_mma2_kernel(
    const float* __restrict__ Q, const float* __restrict__ K,
    const float* __restrict__ V, float* __restrict__ O)
{
    extern __shared__ uint32_t asm4[];
    int tid = threadIdx.x;
    int wid = tid >> 5, lane = tid & 31;
    int gr = lane >> 2, tg = lane & 3;
    int qt = blockIdx.x, h = blockIdx.y, b = blockIdx.z;
    const size_t bh = ((size_t)(b * 16 + h)) * 2048 * 64;
    const int wrow = wid * 32;

    // ---- load Q tile (256 x 64, scale 0.125 folded) -> SMEM tf32
    #pragma unroll
    for (int j = 0; j < 16; j++) {
        int id = tid + j * 256;
        int r = id >> 4, c4 = (id & 15) * 4;
        float4 qv = *(const float4*)(Q + bh + (size_t)(qt * 256 + r) * 64 + c4);
        *(uint4*)(asm4 + A2Q + r * A2STR + c4) =
            make_uint4(f2tf32(qv.x * 0.125f), f2tf32(qv.y * 0.125f),
                       f2tf32(qv.z * 0.125f), f2tf32(qv.w * 0.125f));
    }

    // ---- chunk 0 K/V -> registers -> stage 0
    float4 pk[4], pw[4];
    #pragma unroll
    for (int j = 0; j < 4; j++) {
        int id = tid + j * 256;
        int r = id >> 4, c4 = (id & 15) * 4;
        pk[j] = *(const float4*)(K + bh + (size_t)r * 64 + c4);
        pw[j] = *(const float4*)(V + bh + (size_t)r * 64 + c4);
    }
    #pragma unroll
    for (int j = 0; j < 4; j++) {
        int id = tid + j * 256;
        int r = id >> 4, c4 = (id & 15) * 4;
        *(uint4*)(asm4 + A2KV + r * A2STR + c4) =
            make_uint4(f2tf32(pk[j].x), f2tf32(pk[j].y), f2tf32(pk[j].z), f2tf32(pk[j].w));
        asm4[A2KV + 64 * A2STR + (c4 + 0) * A2STR + r] = f2tf32(pw[j].x);
        asm4[A2KV + 64 * A2STR + (c4 + 1) * A2STR + r] = f2tf32(pw[j].y);
        asm4[A2KV + 64 * A2STR + (c4 + 2) * A2STR + r] = f2tf32(pw[j].z);
        asm4[A2KV + 64 * A2STR + (c4 + 3) * A2STR + r] = f2tf32(pw[j].w);
    }
    // prefetch chunk 1
    #pragma unroll
    for (int j = 0; j < 4; j++) {
        int id = tid + j * 256;
        int r = id >> 4, c4 = (id & 15) * 4;
        pk[j] = *(const float4*)(K + bh + (size_t)(64 + r) * 64 + c4);
        pw[j] = *(const float4*)(V + bh + (size_t)(64 + r) * 64 + c4);
    }
    __syncthreads();

    float mrow[2][2], lrow[2][2];
    #pragma unroll
    for (int mi = 0; mi < 2; mi++) {
        mrow[mi][0] = -1e30f; mrow[mi][1] = -1e30f;
        lrow[mi][0] = 0.0f;   lrow[mi][1] = 0.0f;
    }
    float o[2][8][4];
    #pragma unroll
    for (int mi = 0; mi < 2; mi++)
        #pragma unroll
        for (int j = 0; j < 8; j++)
            #pragma unroll
            for (int r = 0; r < 4; r++) o[mi][j][r] = 0.0f;

    for (int kt = 0; kt < 32; kt++) {
        const uint32_t* Ks = asm4 + A2KV + (kt & 1) * A2KVS;
        const uint32_t* Vs = Ks + 64 * A2STR;

        // ---- S = Q K^T for warp rows [wrow, wrow+32)
        float s[2][8][4];
        #pragma unroll
        for (int mi = 0; mi < 2; mi++)
            #pragma unroll
            for (int j = 0; j < 8; j++)
                #pragma unroll
                for (int r = 0; r < 4; r++) s[mi][j][r] = 0.0f;
        #pragma unroll
        for (int ks = 0; ks < 8; ks++) {
            int kc = ks * 8 + tg;
            uint32_t af[2][4], bf[8][2];
            #pragma unroll
            for (int mi = 0; mi < 2; mi++) {
                int mr = (wrow + mi * 16 + gr) * A2STR;
                af[mi][0] = asm4[A2Q + mr + kc];
                af[mi][1] = asm4[A2Q + mr + 8 * A2STR + kc];
                af[mi][2] = asm4[A2Q + mr + kc + 4];
                af[mi][3] = asm4[A2Q + mr + 8 * A2STR + kc + 4];
            }
            #pragma unroll
            for (int j = 0; j < 8; j++) {
                int nr = (j * 8 + gr) * A2STR;
                bf[j][0] = Ks[nr + kc];
                bf[j][1] = Ks[nr + kc + 4];
            }
            #pragma unroll
            for (int mi = 0; mi < 2; mi++)
                #pragma unroll
                for (int j = 0; j < 8; j++)
                    mma_tf32(s[mi][j], af[mi], bf[j]);
        }

        // ---- online softmax per m-frag (rows gr / gr+8; quad reduce)
        #pragma unroll
        for (int mi = 0; mi < 2; mi++) {
            float mx0 = -1e30f, mx1 = -1e30f;
            #pragma unroll
            for (int j = 0; j < 8; j++) {
                mx0 = fmaxf(mx0, fmaxf(s[mi][j][0], s[mi][j][1]));
                mx1 = fmaxf(mx1, fmaxf(s[mi][j][2], s[mi][j][3]));
            }
            #pragma unroll
            for (int off = 1; off <= 2; off <<= 1) {
                mx0 = fmaxf(mx0, __shfl_xor_sync(0xffffffffu, mx0, off));
                mx1 = fmaxf(mx1, __shfl_xor_sync(0xffffffffu, mx1, off));
            }
            float mn0 = fmaxf(mrow[mi][0], mx0), mn1 = fmaxf(mrow[mi][1], mx1);
            float cr0 = __expf(mrow[mi][0] - mn0), cr1 = __expf(mrow[mi][1] - mn1);
            mrow[mi][0] = mn0; mrow[mi][1] = mn1;
            float sum0 = 0.0f, sum1 = 0.0f;
            int pr = (wrow + mi * 16 + gr) * A2STR;
            #pragma unroll
            for (int j = 0; j < 8; j++) {
                float e00 = __expf(s[mi][j][0] - mn0);
                float e01 = __expf(s[mi][j][1] - mn0);
                float e10 = __expf(s[mi][j][2] - mn1);
                float e11 = __expf(s[mi][j][3] - mn1);
                sum0 += e00 + e01;
                sum1 += e10 + e11;
                int pc = j * 8 + 2 * tg;
                asm4[A2P + pr + pc]     = f2tf32(e00);
                asm4[A2P + pr + pc + 1] = f2tf32(e01);
                asm4[A2P + pr + 8 * A2STR + pc]     = f2tf32(e10);
                asm4[A2P + pr + 8 * A2STR + pc + 1] = f2tf32(e11);
            }
            #pragma unroll
            for (int off = 1; off <= 2; off <<= 1) {
                sum0 += __shfl_xor_sync(0xffffffffu, sum0, off);
                sum1 += __shfl_xor_sync(0xffffffffu, sum1, off);
            }
            lrow[mi][0] = lrow[mi][0] * cr0 + sum0;
            lrow[mi][1] = lrow[mi][1] * cr1 + sum1;
            #pragma unroll
            for (int j = 0; j < 8; j++) {
                o[mi][j][0] *= cr0; o[mi][j][1] *= cr0;
                o[mi][j][2] *= cr1; o[mi][j][3] *= cr1;
            }
        }
        __syncwarp();

        // ---- O += P @ V (A = P rows, B = Vt [d][key])
        #pragma unroll
        for (int ks = 0; ks < 8; ks++) {
            int kc = ks * 8 + tg;
            uint32_t af[2][4], bf[8][2];
            #pragma unroll
            for (int mi = 0; mi < 2; mi++) {
                int mr = (wrow + mi * 16 + gr) * A2STR;
                af[mi][0] = asm4[A2P + mr + kc];
                af[mi][1] = asm4[A2P + mr + 8 * A2STR + kc];
                af[mi][2] = asm4[A2P + mr + kc + 4];
                af[mi][3] = asm4[A2P + mr + 8 * A2STR + kc + 4];
            }
            #pragma unroll
            for (int j = 0; j < 8; j++) {
                int nr = (j * 8 + gr) * A2STR;
                bf[j][0] = Vs[nr + kc];
                bf[j][1] = Vs[nr + kc + 4];
            }
            #pragma unroll
            for (int mi = 0; mi < 2; mi++)
                #pragma unroll
                for (int j = 0; j < 8; j++)
                    mma_tf32(o[mi][j], af[mi], bf[j]);
        }

        // ---- store prefetched chunk into other stage, prefetch next
        if (kt + 1 < 32) {
            uint32_t* Kd = asm4 + A2KV + ((kt + 1) & 1) * A2KVS;
            uint32_t* Vd = Kd + 64 * A2STR;
            #pragma unroll
            for (int j = 0; j < 4; j++) {
                int id = tid + j * 256;
                int r = id >> 4, c4 = (id & 15) * 4;
                *(uint4*)(Kd + r * A2STR + c4) =
                    make_uint4(f2tf32(pk[j].x), f2tf32(pk[j].y), f2tf32(pk[j].z), f2tf32(pk[j].w));
                Vd[(c4 + 0) * A2STR + r] = f2tf32(pw[j].x);
                Vd[(c4 + 1) * A2STR + r] = f2tf32(pw[j].y);
                Vd[(c4 + 2) * A2STR + r] = f2tf32(pw[j].z);
                Vd[(c4 + 3) * A2STR + r] = f2tf32(pw[j].w);
            }
            if (kt + 2 < 32) {
                size_t kb = bh + (size_t)(kt + 2) * 64 * 64;
                #pragma unroll
                for (int j = 0; j < 4; j++) {
                    int id = tid + j * 256;
                    int r = id >> 4, c4 = (id & 15) * 4;
                    pk[j] = *(const float4*)(K + kb + (size_t)r * 64 + c4);
                    pw[j] = *(const float4*)(V + kb + (size_t)r * 64 + c4);
                }
            }
            __syncthreads();
        }
    }

    // ---- finalize and store
    #pragma unroll
    for (int mi = 0; mi < 2; mi++) {
        float inv0 = 1.0f / lrow[mi][0], inv1 = 1.0f / lrow[mi][1];
        int t0 = qt * 256 + wrow + mi * 16 + gr;
        #pragma unroll
        for (int j = 0; j < 8; j++) {
            int cn = h * 64 + j * 8 + 2 * tg;
            *(float2*)(O + (size_t)(b * 2048 + t0) * 1024 + cn) =
                make_float2(o[mi][j][0] * inv0, o[mi][j][1] * inv0);
            *(float2*)(O + (size_t)(b * 2048 + t0 + 8) * 1024 + cn) =
                make_float2(o[mi][j][2] * inv1, o[mi][j][3] * inv1);
        }
    }
}

// ---------------------------------------------------------------------------
// MLP activation
// ---------------------------------------------------------------------------
__global__ void __launch_bounds__(256) mlp_act_kernel(
    const float* __restrict__ fc1, float* __restrict__ mid)
{
    int f = blockIdx.x * 256 + threadIdx.x;
    int row = f >> 10;
    int jcol = (f & 1023) * 4;
    float4 v = *(const float4*)(fc1 + (size_t)row * 8192 + jcol);
    float4 g = *(const float4*)(fc1 + (size_t)row * 8192 + 4096 + jcol);
    float4 o;
    o.x = v.x * g.x / (1.0f + __expf(-g.x));
    o.y = v.y * g.y / (1.0f + __expf(-g.y));
    o.z = v.z * g.z / (1.0f + __expf(-g.z));
    o.w = v.w * g.w / (1.0f + __expf(-g.w));
    *(float4*)(mid + (size_t)row * 4096 + jcol) = o;
}

// ---------------------------------------------------------------------------
// Launch
// ---------------------------------------------------------------------------
extern "C" void kernel_launch(void* const* d_in, const int* in_sizes, int n_in,
                              void* d_out, int out_size)
{
    const float* x        = (const float*)d_in[0];
    const float* cond     = (const float*)d_in[1];
    const float* norm1_w  = (const float*)d_in[2];
    const float* qkv_w    = (const float*)d_in[3];
    const float* q_norm_w = (const float*)d_in[4];
    const float* k_norm_w = (const float*)d_in[5];
    const float* proj_w   = (const float*)d_in[6];
    const float* proj_b   = (const float*)d_in[7];
    const float* norm2_w  = (const float*)d_in[8];
    const float* fc1_w    = (const float*)d_in[9];
    const float* fc1_b    = (const float*)d_in[10];
    const float* fc2_w    = (const float*)d_in[11];
    const float* fc2_b    = (const float*)d_in[12];
    const float* ada_w    = (const float*)d_in[13];
    const float* ada_b    = (const float*)d_in[14];
    const int*   widthp   = (const int*)d_in[16];
    float* out = (float*)d_out;

    float *p_ada, *p_h, *p_qkv, *p_q, *p_k, *p_v, *p_attn, *p_xa, *p_h2, *p_fc1, *p_mid;
    cudaGetSymbolAddress((void**)&p_ada, g_ada);
    cudaGetSymbolAddress((void**)&p_h, g_h);
    cudaGetSymbolAddress((void**)&p_qkv, g_qkv);
    cudaGetSymbolAddress((void**)&p_q, g_q);
    cudaGetSymbolAddress((void**)&p_k, g_k);
    cudaGetSymbolAddress((void**)&p_v, g_v);
    cudaGetSymbolAddress((void**)&p_attn, g_attn);
    cudaGetSymbolAddress((void**)&p_xa, g_xa);
    cudaGetSymbolAddress((void**)&p_h2, g_h2);
    cudaGetSymbolAddress((void**)&p_fc1, g_fc1);
    cudaGetSymbolAddress((void**)&p_mid, g_mid);

    int attn_smem = ATT2_SMEMW * 4;
    cudaFuncSetAttribute(attn_mma2_kernel, cudaFuncAttributeMaxDynamicSharedMemorySize, attn_smem);
    cudaFuncSetAttribute(gemm_mma, cudaFuncAttributeMaxDynamicSharedMemorySize, GT_DSMEM);

    // 1) adaLN
    ada_kernel<<<1536, 256>>>(cond, ada_w, ada_b, p_ada);
    // 2) norm1 + modulate
    norm_mod_kernel<<<4096, 256>>>(x, p_h, norm1_w, p_ada, 0, 1024);
    // 3) QKV GEMM
    gemm_mma<<<dim3(3072 / 128, 4096 / 128), 256, GT_DSMEM>>>(p_h, qkv_w, p_qkv,
        4096, 3072, 1024, nullptr, nullptr, nullptr, 0);
    // 4) QK norm + RoPE + transpose
    qkv_post_kernel<<<8192, 256>>>(p_qkv, p_q, p_k, p_v, q_norm_w, k_norm_w, widthp);
    // 5) attention (tf32 mma, v2)
    attn_mma2_kernel<<<dim3(8, 16, 2), 256, attn_smem>>>(p_q, p_k, p_v, p_attn);
    // 6) proj GEMM + residual + gate
    gemm_mma<<<dim3(1024 / 128, 4096 / 128), 256, GT_DSMEM>>>(p_attn, proj_w, p_xa,
        4096, 1024, 1024, proj_b, x, p_ada, 2 * 1024);
    // 7) norm2 + modulate
    norm_mod_kernel<<<4096, 256>>>(p_xa, p_h2, norm2_w, p_ada, 3 * 1024, 4 * 1024);
    // 8) fc1 GEMM
    gemm_mma<<<dim3(8192 / 128, 4096 / 128), 256, GT_DSMEM>>>(p_h2, fc1_w, p_fc1,
        4096, 8192, 1024, fc1_b, nullptr, nullptr, 0);
    // 9) value * silu(gate)
    mlp_act_kernel<<<16384, 256>>>(p_fc1, p_mid);
    // 10) fc2 GEMM + residual + gate -> out
    gemm_mma<<<dim3(1024 / 128, 4096 / 128), 256, GT_DSMEM>>>(p_mid, fc2_w, out,
        4096, 1024, 4096, fc2_b, p_xa, p_ada, 5 * 1024);
}